// round 13
// baseline (speedup 1.0000x reference)
#include <cuda_runtime.h>
#include <cuda_bf16.h>
#include <cstdint>
#include <math.h>

#define B_     2
#define L_     2048
#define HID_   4096
#define NHEAD_ 32
#define NKV_   8
#define HDIM_  128
#define MROWS  (B_*L_)          // 4096
#define KVW    (2*NKV_*HDIM_)   // 2048
#define VW     (NKV_*HDIM_)     // 1024

// ------------------------- device scratch (no allocs) -----------------------
__device__ __align__(256) float g_v  [(size_t)MROWS * VW];   // V fp32 (16 MB)

__device__ __align__(256) __nv_bfloat16 g_qin_h [(size_t)MROWS * HID_];
__device__ __align__(256) __nv_bfloat16 g_qin_l [(size_t)MROWS * HID_];
__device__ __align__(256) __nv_bfloat16 g_kvin_h[(size_t)MROWS * HID_];
__device__ __align__(256) __nv_bfloat16 g_kvin_l[(size_t)MROWS * HID_];
__device__ __align__(256) __nv_bfloat16 g_att_h [(size_t)MROWS * HID_];
__device__ __align__(256) __nv_bfloat16 g_att_l [(size_t)MROWS * HID_];
__device__ __align__(256) __nv_bfloat16 g_wqt_h [(size_t)HID_ * HID_];
__device__ __align__(256) __nv_bfloat16 g_wqt_l [(size_t)HID_ * HID_];
__device__ __align__(256) __nv_bfloat16 g_wkvt_h[(size_t)KVW  * HID_];
__device__ __align__(256) __nv_bfloat16 g_wkvt_l[(size_t)KVW  * HID_];
__device__ __align__(256) __nv_bfloat16 g_wot_h [(size_t)HID_ * HID_];
__device__ __align__(256) __nv_bfloat16 g_wot_l [(size_t)HID_ * HID_];
// attention operands (bf16 hi/lo)
__device__ __align__(256) __nv_bfloat16 g_aqh[(size_t)MROWS * HID_];  // scaled Q
__device__ __align__(256) __nv_bfloat16 g_aql[(size_t)MROWS * HID_];
__device__ __align__(256) __nv_bfloat16 g_kh [(size_t)B_*NKV_*L_*HDIM_]; // [b,kvh,l,d]
__device__ __align__(256) __nv_bfloat16 g_kl [(size_t)B_*NKV_*L_*HDIM_];
__device__ __align__(256) __nv_bfloat16 g_vth[(size_t)B_*NKV_*HDIM_*L_]; // [b,kvh,d,l]
__device__ __align__(256) __nv_bfloat16 g_vtl[(size_t)B_*NKV_*HDIM_*L_];

// ------------------------------ PTX helpers ---------------------------------
__device__ __forceinline__ uint32_t smem_u32(const void* p) {
    uint32_t a;
    asm("{ .reg .u64 t; cvta.to.shared.u64 t, %1; cvt.u32.u64 %0, t; }"
        : "=r"(a) : "l"(p));
    return a;
}

__device__ __forceinline__ void ldsm4(uint32_t* r, uint32_t addr) {
    asm volatile("ldmatrix.sync.aligned.m8n8.x4.shared.b16 {%0,%1,%2,%3}, [%4];"
                 : "=r"(r[0]), "=r"(r[1]), "=r"(r[2]), "=r"(r[3]) : "r"(addr));
}

__device__ __forceinline__ void mma16816(float* d, const uint32_t* a,
                                         const uint32_t* b) {
    asm volatile(
        "mma.sync.aligned.m16n8k16.row.col.f32.bf16.bf16.f32 "
        "{%0,%1,%2,%3}, {%4,%5,%6,%7}, {%8,%9}, {%0,%1,%2,%3};"
        : "+f"(d[0]), "+f"(d[1]), "+f"(d[2]), "+f"(d[3])
        : "r"(a[0]), "r"(a[1]), "r"(a[2]), "r"(a[3]), "r"(b[0]), "r"(b[1]));
}

#define CP16(saddr, gaddr) \
    asm volatile("cp.async.cg.shared.global [%0], [%1], 16;" \
                 :: "r"(saddr), "l"(gaddr) : "memory")
#define CP_COMMIT()  asm volatile("cp.async.commit_group;" ::: "memory")
#define CP_WAIT0()   asm volatile("cp.async.wait_group 0;" ::: "memory")
#define CP_WAIT1()   asm volatile("cp.async.wait_group 1;" ::: "memory")

__device__ __forceinline__ unsigned short f2bf_bits(float x) {
    __nv_bfloat16 h = __float2bfloat16(x);
    return *(unsigned short*)&h;
}
__device__ __forceinline__ float bf_bits2f(unsigned short b) {
    __nv_bfloat16 h = *(__nv_bfloat16*)&b;
    return __bfloat162float(h);
}
__device__ __forceinline__ uint32_t pack_hi(float a, float b) {
    return (uint32_t)f2bf_bits(a) | ((uint32_t)f2bf_bits(b) << 16);
}
__device__ __forceinline__ uint32_t pack_lo(float a, float b) {
    unsigned short ha = f2bf_bits(a), hb = f2bf_bits(b);
    return (uint32_t)f2bf_bits(a - bf_bits2f(ha))
         | ((uint32_t)f2bf_bits(b - bf_bits2f(hb)) << 16);
}

// ---------------------------- conversion kernels ----------------------------
__global__ __launch_bounds__(256) void split_k(const float* __restrict__ in,
                                               __nv_bfloat16* __restrict__ hi,
                                               __nv_bfloat16* __restrict__ lo,
                                               int n4, float scale)
{
    int i = blockIdx.x * 256 + threadIdx.x;
    if (i >= n4) return;
    float4 v = ((const float4*)in)[i];
    v.x *= scale; v.y *= scale; v.z *= scale; v.w *= scale;
    ((uint2*)hi)[i] = make_uint2(pack_hi(v.x, v.y), pack_hi(v.z, v.w));
    ((uint2*)lo)[i] = make_uint2(pack_lo(v.x, v.y), pack_lo(v.z, v.w));
}

// W[K][N] fp32 -> Wt_hi/lo[N][K] bf16 (tiled transpose)
__global__ __launch_bounds__(256) void tsplit_k(const float* __restrict__ W,
                                                __nv_bfloat16* __restrict__ Th,
                                                __nv_bfloat16* __restrict__ Tl,
                                                int K, int N)
{
    __shared__ float t[32][33];
    int tx = threadIdx.x, ty = threadIdx.y;   // 32 x 8
    int n0 = blockIdx.x * 32, k0 = blockIdx.y * 32;
#pragma unroll
    for (int i = 0; i < 4; i++)
        t[ty + 8 * i][tx] = W[(size_t)(k0 + ty + 8 * i) * N + n0 + tx];
    __syncthreads();
#pragma unroll
    for (int i = 0; i < 4; i++) {
        float v = t[tx][ty + 8 * i];
        unsigned short h = f2bf_bits(v);
        unsigned short l = f2bf_bits(v - bf_bits2f(h));
        size_t o = (size_t)(n0 + ty + 8 * i) * K + k0 + tx;
        Th[o] = *(__nv_bfloat16*)&h; Tl[o] = *(__nv_bfloat16*)&l;
    }
}

// V prep: g_v fp32 [b*L+l][kvh*128+d] -> vth/vtl [b,kvh,d,l] bf16 (transpose)
__global__ __launch_bounds__(256) void vtprep_k(const float* __restrict__ V,
                                                __nv_bfloat16* __restrict__ Vh,
                                                __nv_bfloat16* __restrict__ Vl)
{
    __shared__ float t[32][33];
    int tx = threadIdx.x, ty = threadIdx.y;
    int l0 = blockIdx.x * 32, d0 = blockIdx.y * 32;
    int bk = blockIdx.z;
    int b = bk >> 3, kvh = bk & 7;
#pragma unroll
    for (int i = 0; i < 4; i++)
        t[ty + 8 * i][tx] = V[(size_t)(b * L_ + l0 + ty + 8 * i) * VW
                              + kvh * HDIM_ + d0 + tx];
    __syncthreads();
#pragma unroll
    for (int i = 0; i < 4; i++) {
        float v = t[tx][ty + 8 * i];
        unsigned short h = f2bf_bits(v);
        unsigned short l = f2bf_bits(v - bf_bits2f(h));
        size_t o = ((size_t)bk * HDIM_ + d0 + ty + 8 * i) * L_ + l0 + tx;
        Vh[o] = *(__nv_bfloat16*)&h; Vl[o] = *(__nv_bfloat16*)&l;
    }
}

// -------- HMMA GEMM: 128x256 tile, 512 threads, 3-stage cp.async ------------
// 16 warps (4m x 4n), warp tile 32x64. Prefetch distance 2 -> copies hidden.
#define SSTRIDE 40
#define A_OFF   0u
#define AL_OFF  10240u                 // 128*40*2
#define BH_OFF  20480u
#define BL_OFF  40960u                 // BH + 256*40*2
#define STAGE3B 61440u                 // per-stage bytes
#define GEMM_DSMEM (3 * (int)STAGE3B)  // 184320 B

__global__ __launch_bounds__(512) void hgemm_db_k(
    const __nv_bfloat16* __restrict__ Ah, const __nv_bfloat16* __restrict__ Al,
    const __nv_bfloat16* __restrict__ Bh, const __nv_bfloat16* __restrict__ Bl,
    const float* __restrict__ bias,
    float* __restrict__ C,
    __nv_bfloat16* __restrict__ Ch, __nv_bfloat16* __restrict__ Cl,
    float oscale, int M, int N, int K, int mode)
{
    extern __shared__ __nv_bfloat16 dynsm[];
    const uint32_t sbase = smem_u32(dynsm);

    const int tid  = threadIdx.x;
    const int wid  = tid >> 5, lane = tid & 31;
    const int gr   = lane >> 2, tg = lane & 3;
    const int wm   = (wid & 3) * 32;       // warp M origin (4 warps over 128)
    const int wn   = (wid >> 2) * 64;      // warp N origin (4 warps over 256)
    const int row0 = blockIdx.y * 128, col0 = blockIdx.x * 256;
    const int q    = lane >> 3, rr = lane & 7;

    float acc[2][8][4];
#pragma unroll
    for (int mt = 0; mt < 2; mt++)
#pragma unroll
        for (int nt = 0; nt < 8; nt++)
#pragma unroll
            for (int e = 0; e < 4; e++) acc[mt][nt][e] = 0.f;

    // loaders: A 128x32 (1 chunk/thread per array), B 256x32 (2 chunks/thread)
    const int arow = tid >> 2, ach = (tid & 3) * 8;
    const uint32_t soA = (uint32_t)(arow * SSTRIDE + ach) * 2;
    const __nv_bfloat16* pAh = Ah + (size_t)row0 * K;
    const __nv_bfloat16* pAl = Al + (size_t)row0 * K;
    const __nv_bfloat16* pBh = Bh + (size_t)col0 * K;
    const __nv_bfloat16* pBl = Bl + (size_t)col0 * K;

    const int niter = K >> 5;

    auto issue = [&](uint32_t bb, int it) {
        const int kt = it << 5;
        CP16(bb + A_OFF  + soA, pAh + (size_t)arow * K + kt + ach);
        CP16(bb + AL_OFF + soA, pAl + (size_t)arow * K + kt + ach);
#pragma unroll
        for (int i = 0; i < 2; i++) {
            int idx = tid + i * 512;
            int brow = idx >> 2, bch = (idx & 3) * 8;
            uint32_t soB = (uint32_t)(brow * SSTRIDE + bch) * 2;
            CP16(bb + BH_OFF + soB, pBh + (size_t)brow * K + kt + bch);
            CP16(bb + BL_OFF + soB, pBl + (size_t)brow * K + kt + bch);
        }
    };

    issue(sbase, 0); CP_COMMIT();
    issue(sbase + STAGE3B, 1); CP_COMMIT();

    for (int it = 0; it < niter; ++it) {
        const uint32_t st = sbase + (uint32_t)(it % 3) * STAGE3B;
        if (it + 1 < niter) CP_WAIT1(); else CP_WAIT0();
        __syncthreads();                     // all warps done with stage (it-1)%3
        if (it + 2 < niter) { issue(sbase + (uint32_t)((it + 2) % 3) * STAGE3B, it + 2); CP_COMMIT(); }

        const uint32_t aAh = st + A_OFF, aAl = st + AL_OFF;
        const uint32_t aBh = st + BH_OFF, aBl = st + BL_OFF;

#pragma unroll
        for (int ks = 0; ks < 2; ++ks) {
            // resident A fragments (2 m-tiles, hi+lo = 16 regs)
            uint32_t fAh[2][4], fAl[2][4];
#pragma unroll
            for (int mt = 0; mt < 2; ++mt) {
                uint32_t offa = (uint32_t)((wm + mt * 16 + (q & 1) * 8 + rr) * (SSTRIDE * 2)
                                           + (ks * 16 + (q >> 1) * 8) * 2);
                ldsm4(fAh[mt], aAh + offa);
                ldsm4(fAl[mt], aAl + offa);
            }
            // stream B fragments (4 pairs of 16 n-cols)
#pragma unroll
            for (int np = 0; np < 4; ++np) {
                uint32_t offb = (uint32_t)((wn + np * 16 + (q >> 1) * 8 + rr) * (SSTRIDE * 2)
                                           + (ks * 16 + (q & 1) * 8) * 2);
                uint32_t fBh[4], fBl[4];
                ldsm4(fBh, aBh + offb);
                ldsm4(fBl, aBl + offb);
#pragma unroll
                for (int mt = 0; mt < 2; ++mt) {
                    float* a0 = acc[mt][np * 2];
                    float* a1 = acc[mt][np * 2 + 1];
                    mma16816(a0, fAh[mt], &fBh[0]);
                    mma16816(a1, fAh[mt], &fBh[2]);
                    mma16816(a0, fAl[mt], &fBh[0]);
                    mma16816(a1, fAl[mt], &fBh[2]);
                    mma16816(a0, fAh[mt], &fBl[0]);
                    mma16816(a1, fAh[mt], &fBl[2]);
                }
            }
        }
    }

    // ---- epilogue ----
    const bool kv_kpart = (mode == 2) && (col0 < VW);
    if (mode == 1 || kv_kpart) {
#pragma unroll
        for (int mt = 0; mt < 2; ++mt) {
#pragma unroll
            for (int nt = 0; nt < 8; ++nt) {
                int r = row0 + wm + mt * 16 + gr;
                int c = col0 + wn + nt * 8 + tg * 2;
                float b0 = bias[c], b1 = bias[c + 1];
                float v0 = (acc[mt][nt][0] + b0) * oscale;
                float v1 = (acc[mt][nt][1] + b1) * oscale;
                float v2 = (acc[mt][nt][2] + b0) * oscale;
                float v3 = (acc[mt][nt][3] + b1) * oscale;
                size_t o0, o1;
                if (kv_kpart) {
                    int bb = r >> 11, ll = r & (L_ - 1);
                    int kvhh = c >> 7, d = c & (HDIM_ - 1);
                    o0 = ((size_t)(bb * NKV_ + kvhh) * L_ + ll) * HDIM_ + d;
                    o1 = o0 + (size_t)8 * HDIM_;
                } else {
                    o0 = (size_t)r * N + c;
                    o1 = (size_t)(r + 8) * N + c;
                }
                *(uint32_t*)(Ch + o0) = pack_hi(v0, v1);
                *(uint32_t*)(Cl + o0) = pack_lo(v0, v1);
                *(uint32_t*)(Ch + o1) = pack_hi(v2, v3);
                *(uint32_t*)(Cl + o1) = pack_lo(v2, v3);
            }
        }
    } else {
        const int cw    = (mode == 2) ? VW : N;
        const int cbase = (mode == 2) ? (col0 - VW) : col0;
#pragma unroll
        for (int mt = 0; mt < 2; ++mt) {
#pragma unroll
            for (int nt = 0; nt < 8; ++nt) {
                int r = row0 + wm + mt * 16 + gr;
                int c = col0 + wn + nt * 8 + tg * 2;
                float b0 = bias[c], b1 = bias[c + 1];
                int cc = cbase + wn + nt * 8 + tg * 2;
                float2 v0 = make_float2(acc[mt][nt][0] + b0, acc[mt][nt][1] + b1);
                float2 v1 = make_float2(acc[mt][nt][2] + b0, acc[mt][nt][3] + b1);
                *(float2*)(C + (size_t)r * cw + cc) = v0;
                *(float2*)(C + (size_t)(r + 8) * cw + cc) = v1;
            }
        }
    }
}

// ---------------------------------------------------------------------------
// Tensor-core flash attention — validated R12 version (double-buffered V,
// mid-iteration K refill, register-resident Q).
// ---------------------------------------------------------------------------
#define QSTR 136
#define VSTR 72
#define KPAIR_B  (2u * 64 * QSTR * 2)
#define VPAIR_B  (2u * 128 * VSTR * 2)
#define ATT_SMEM ((int)(KPAIR_B + 2 * VPAIR_B))   // 108544 B

__global__ __launch_bounds__(128) void attn_tc_k(
    const __nv_bfloat16* __restrict__ Qh, const __nv_bfloat16* __restrict__ Ql,
    const __nv_bfloat16* __restrict__ Kh, const __nv_bfloat16* __restrict__ Kl,
    const __nv_bfloat16* __restrict__ Vh, const __nv_bfloat16* __restrict__ Vl,
    __nv_bfloat16* __restrict__ Oh, __nv_bfloat16* __restrict__ Ol)
{
    extern __shared__ __nv_bfloat16 smem_bf[];
    const uint32_t sb  = smem_u32(smem_bf);
    const uint32_t aKh = sb;
    const uint32_t aKl = aKh + 64 * QSTR * 2;
    const uint32_t aV0 = aKl + 64 * QSTR * 2;
    const uint32_t aV1 = aV0 + VPAIR_B;

    const int b = blockIdx.z, head = blockIdx.y, qt = blockIdx.x;
    const int kvh = head >> 2;
    const int tid = threadIdx.x;
    const int wid = tid >> 5, lane = tid & 31;
    const int q = lane >> 3, rr = lane & 7;
    const int gr = lane >> 2, tg = lane & 3;

    const __nv_bfloat16* kbh = Kh + (size_t)(b * NKV_ + kvh) * L_ * HDIM_;
    const __nv_bfloat16* kbl = Kl + (size_t)(b * NKV_ + kvh) * L_ * HDIM_;
    const __nv_bfloat16* vbh = Vh + (size_t)(b * NKV_ + kvh) * HDIM_ * L_;
    const __nv_bfloat16* vbl = Vl + (size_t)(b * NKV_ + kvh) * HDIM_ * L_;

    auto issueK = [&](int t) {
#pragma unroll
        for (int i = 0; i < 8; i++) {
            int idx = tid + i * 128;
            int row = idx >> 4, ch = idx & 15;
            uint32_t so = (uint32_t)(row * QSTR + ch * 8) * 2;
            CP16(aKh + so, kbh + (size_t)(t * 64 + row) * HDIM_ + ch * 8);
            CP16(aKl + so, kbl + (size_t)(t * 64 + row) * HDIM_ + ch * 8);
        }
    };
    auto issueV = [&](int t, uint32_t vb) {
#pragma unroll
        for (int i = 0; i < 8; i++) {
            int idx = tid + i * 128;
            int vrow = idx >> 3, vch = idx & 7;
            uint32_t so = (uint32_t)(vrow * VSTR + vch * 8) * 2;
            CP16(vb + so,                   vbh + (size_t)vrow * L_ + t * 64 + vch * 8);
            CP16(vb + 128 * VSTR * 2 + so,  vbl + (size_t)vrow * L_ + t * 64 + vch * 8);
        }
    };

    {
        const __nv_bfloat16* qbh = Qh + (size_t)(b * L_ + qt * 64) * HID_ + head * HDIM_;
        const __nv_bfloat16* qbl = Ql + (size_t)(b * L_ + qt * 64) * HID_ + head * HDIM_;
#pragma unroll
        for (int i = 0; i < 8; i++) {
            int idx = tid + i * 128;
            int row = idx >> 4, ch = idx & 15;
            uint32_t so = (uint32_t)(row * QSTR + ch * 8) * 2;
            CP16(aKh + so, qbh + (size_t)row * HID_ + ch * 8);
            CP16(aKl + so, qbl + (size_t)row * HID_ + ch * 8);
        }
        CP_COMMIT(); CP_WAIT0();
    }
    __syncthreads();
    uint32_t fQh[8][4], fQl[8][4];
#pragma unroll
    for (int ks = 0; ks < 8; ++ks) {
        uint32_t aoff = (uint32_t)((wid * 16 + (q & 1) * 8 + rr) * (QSTR * 2)
                                   + (ks * 16 + (q >> 1) * 8) * 2);
        ldsm4(fQh[ks], aKh + aoff);
        ldsm4(fQl[ks], aKl + aoff);
    }
    __syncthreads();

    issueK(0); issueV(0, aV0); CP_COMMIT();

    float oacc[16][4];
#pragma unroll
    for (int nt = 0; nt < 16; nt++)
#pragma unroll
        for (int e = 0; e < 4; e++) oacc[nt][e] = 0.f;
    float m0 = -1e30f, m1 = -1e30f, l0 = 0.f, l1 = 0.f;

    const int NT = L_ / 64;
    for (int t = 0; t < NT; ++t) {
        const uint32_t vcur = (t & 1) ? aV1 : aV0;
        const uint32_t vnxt = (t & 1) ? aV0 : aV1;

        CP_WAIT0();
        __syncthreads();

        if (t + 1 < NT) { issueV(t + 1, vnxt); CP_COMMIT(); }

        float sacc[8][4];
#pragma unroll
        for (int nt = 0; nt < 8; nt++)
#pragma unroll
            for (int e = 0; e < 4; e++) sacc[nt][e] = 0.f;

#pragma unroll
        for (int ks = 0; ks < 8; ++ks) {
            uint32_t fKh[4][4], fKl[4][4];
#pragma unroll
            for (int np = 0; np < 4; ++np) {
                uint32_t boff = (uint32_t)((np * 16 + (q >> 1) * 8 + rr) * (QSTR * 2)
                                           + (ks * 16 + (q & 1) * 8) * 2);
                ldsm4(fKh[np], aKh + boff);
                ldsm4(fKl[np], aKl + boff);
            }
#pragma unroll
            for (int nt = 0; nt < 8; ++nt) {
                const uint32_t* bh = &fKh[nt >> 1][(nt & 1) * 2];
                const uint32_t* bl = &fKl[nt >> 1][(nt & 1) * 2];
                mma16816(sacc[nt], fQh[ks], bh);
                mma16816(sacc[nt], fQl[ks], bh);
                mma16816(sacc[nt], fQh[ks], bl);
            }
        }
        __syncthreads();
        if (t + 1 < NT) { issueK(t + 1); CP_COMMIT(); }

        float rmax0 = -1e30f, rmax1 = -1e30f;
#pragma unroll
        for (int nt = 0; nt < 8; ++nt) {
            rmax0 = fmaxf(rmax0, fmaxf(sacc[nt][0], sacc[nt][1]));
            rmax1 = fmaxf(rmax1, fmaxf(sacc[nt][2], sacc[nt][3]));
        }
        rmax0 = fmaxf(rmax0, __shfl_xor_sync(0xffffffffu, rmax0, 1));
        rmax0 = fmaxf(rmax0, __shfl_xor_sync(0xffffffffu, rmax0, 2));
        rmax1 = fmaxf(rmax1, __shfl_xor_sync(0xffffffffu, rmax1, 1));
        rmax1 = fmaxf(rmax1, __shfl_xor_sync(0xffffffffu, rmax1, 2));
        float mn0 = fmaxf(m0, rmax0), mn1 = fmaxf(m1, rmax1);
        float fact0 = __expf(m0 - mn0), fact1 = __expf(m1 - mn1);
        m0 = mn0; m1 = mn1;
        float sum0 = 0.f, sum1 = 0.f;
#pragma unroll
        for (int nt = 0; nt < 8; ++nt) {
            sacc[nt][0] = __expf(sacc[nt][0] - mn0); sum0 += sacc[nt][0];
            sacc[nt][1] = __expf(sacc[nt][1] - mn0); sum0 += sacc[nt][1];
            sacc[nt][2] = __expf(sacc[nt][2] - mn1); sum1 += sacc[nt][2];
            sacc[nt][3] = __expf(sacc[nt][3] - mn1); sum1 += sacc[nt][3];
        }
        sum0 += __shfl_xor_sync(0xffffffffu, sum0, 1);
        sum0 += __shfl_xor_sync(0xffffffffu, sum0, 2);
        sum1 += __shfl_xor_sync(0xffffffffu, sum1, 1);
        sum1 += __shfl_xor_sync(0xffffffffu, sum1, 2);
        l0 = l0 * fact0 + sum0;
        l1 = l1 * fact1 + sum1;
#pragma unroll
        for (int nt = 0; nt < 16; ++nt) {
            oacc[nt][0] *= fact0; oacc[nt][1] *= fact0;
            oacc[nt][2] *= fact1; oacc[nt][3] *= fact1;
        }

        const uint32_t aVhc = vcur, aVlc = vcur + 128 * VSTR * 2;
#pragma unroll
        for (int j = 0; j < 4; ++j) {
            uint32_t aPh[4], aPl[4];
#pragma unroll
            for (int hlf = 0; hlf < 2; ++hlf) {
                const float* p = sacc[2 * j + hlf];
                aPh[2 * hlf]     = pack_hi(p[0], p[1]);
                aPh[2 * hlf + 1] = pack_hi(p[2], p[3]);
                aPl[2 * hlf]     = pack_lo(p[0], p[1]);
                aPl[2 * hlf + 1] = pack_lo(p[2], p[3]);
            }
#pragma unroll
            for (int nn = 0; nn < 8; ++nn) {
                uint32_t fVh[4], fVl[4];
                uint32_t voff = (uint32_t)((nn * 16 + (q >> 1) * 8 + rr) * (VSTR * 2)
                                           + (j * 16 + (q & 1) * 8) * 2);
                ldsm4(fVh, aVhc + voff);
                ldsm4(fVl, aVlc + voff);
                mma16816(oacc[2 * nn], aPh, &fVh[0]);
                mma16816(oacc[2 * nn], aPl, &fVh[0]);
                mma16816(oacc[2 * nn], aPh, &fVl[0]);
                mma16816(oacc[2 * nn + 1], aPh, &fVh[2]);
                mma16816(oacc[2 * nn + 1], aPl, &fVh[2]);
                mma16816(oacc[2 * nn + 1], aPh, &fVl[2]);
            }
        }
    }

    float inv0 = 1.0f / l0, inv1 = 1.0f / l1;
    const int row0g = b * L_ + qt * 64 + wid * 16 + gr;
    __nv_bfloat16* oh0 = Oh + (size_t)row0g * HID_ + head * HDIM_;
    __nv_bfloat16* ol0 = Ol + (size_t)row0g * HID_ + head * HDIM_;
    __nv_bfloat16* oh1 = oh0 + (size_t)8 * HID_;
    __nv_bfloat16* ol1 = ol0 + (size_t)8 * HID_;
#pragma unroll
    for (int nt = 0; nt < 16; ++nt) {
        int col = nt * 8 + tg * 2;
        float v0 = oacc[nt][0] * inv0, v1 = oacc[nt][1] * inv0;
        float v2 = oacc[nt][2] * inv1, v3 = oacc[nt][3] * inv1;
        *(uint32_t*)(oh0 + col) = pack_hi(v0, v1);
        *(uint32_t*)(ol0 + col) = pack_lo(v0, v1);
        *(uint32_t*)(oh1 + col) = pack_hi(v2, v3);
        *(uint32_t*)(ol1 + col) = pack_lo(v2, v3);
    }
}

// ---------------------------------------------------------------------------
extern "C" void kernel_launch(void* const* d_in, const int* in_sizes, int n_in,
                              void* d_out, int out_size)
{
    const float* query = (const float*)d_in[0];
    const float* kv    = (const float*)d_in[1];
    const float* Wq    = (const float*)d_in[2];
    const float* bq    = (const float*)d_in[3];
    const float* Wkv   = (const float*)d_in[4];
    const float* bkv   = (const float*)d_in[5];
    const float* Wo    = (const float*)d_in[6];
    const float* bo    = (const float*)d_in[7];
    float* out = (float*)d_out;

    float* pv = nullptr;
    cudaGetSymbolAddress((void**)&pv, g_v);
    __nv_bfloat16 *qh, *ql, *kvh, *kvl, *ath, *atl;
    __nv_bfloat16 *wqh, *wql, *wkh, *wkl, *woh, *wol;
    __nv_bfloat16 *aqh, *aql, *akh, *akl, *avh, *avl;
    cudaGetSymbolAddress((void**)&qh,  g_qin_h);  cudaGetSymbolAddress((void**)&ql,  g_qin_l);
    cudaGetSymbolAddress((void**)&kvh, g_kvin_h); cudaGetSymbolAddress((void**)&kvl, g_kvin_l);
    cudaGetSymbolAddress((void**)&ath, g_att_h);  cudaGetSymbolAddress((void**)&atl, g_att_l);
    cudaGetSymbolAddress((void**)&wqh, g_wqt_h);  cudaGetSymbolAddress((void**)&wql, g_wqt_l);
    cudaGetSymbolAddress((void**)&wkh, g_wkvt_h); cudaGetSymbolAddress((void**)&wkl, g_wkvt_l);
    cudaGetSymbolAddress((void**)&woh, g_wot_h);  cudaGetSymbolAddress((void**)&wol, g_wot_l);
    cudaGetSymbolAddress((void**)&aqh, g_aqh);    cudaGetSymbolAddress((void**)&aql, g_aql);
    cudaGetSymbolAddress((void**)&akh, g_kh);     cudaGetSymbolAddress((void**)&akl, g_kl);
    cudaGetSymbolAddress((void**)&avh, g_vth);    cudaGetSymbolAddress((void**)&avl, g_vtl);

    cudaFuncSetAttribute(attn_tc_k, cudaFuncAttributeMaxDynamicSharedMemorySize,
                         ATT_SMEM);
    cudaFuncSetAttribute(hgemm_db_k, cudaFuncAttributeMaxDynamicSharedMemorySize,
                         GEMM_DSMEM);

    const int n_act4 = (MROWS * HID_) / 4;
    const float qscale = 0.08838834764831845f;   // 1/sqrt(128)

    split_k<<<(n_act4 + 255) / 256, 256>>>(query, qh, ql, n_act4, 1.0f);            // 0
    tsplit_k<<<dim3(HID_ / 32, HID_ / 32), dim3(32, 8)>>>(Wq, wqh, wql, HID_, HID_); // 1
    split_k<<<(n_act4 + 255) / 256, 256>>>(kv, kvh, kvl, n_act4, 1.0f);             // 2
    // 3: Q projection (ncu capture slot)
    hgemm_db_k<<<dim3(HID_ / 256, MROWS / 128), 512, GEMM_DSMEM>>>(
        qh, ql, wqh, wql, bq, nullptr, aqh, aql, qscale, MROWS, HID_, HID_, 1);
    tsplit_k<<<dim3(KVW / 32, HID_ / 32), dim3(32, 8)>>>(Wkv, wkh, wkl, HID_, KVW); // 4
    // 5: KV projection -> K [b,kvh,l,d] bf16 hi/lo; V fp32
    hgemm_db_k<<<dim3(KVW / 256, MROWS / 128), 512, GEMM_DSMEM>>>(
        kvh, kvl, wkh, wkl, bkv, pv, akh, akl, 1.0f, MROWS, KVW, HID_, 2);
    tsplit_k<<<dim3(HID_ / 32, HID_ / 32), dim3(32, 8)>>>(Wo, woh, wol, HID_, HID_); // 6
    vtprep_k<<<dim3(L_ / 32, HDIM_ / 32, B_ * NKV_), dim3(32, 8)>>>(pv, avh, avl);   // 7
    // 8: tensor-core attention
    attn_tc_k<<<dim3(L_ / 64, NHEAD_, B_), 128, ATT_SMEM>>>(
        aqh, aql, akh, akl, avh, avl, ath, atl);
    // 9: O projection -> fp32 out
    hgemm_db_k<<<dim3(HID_ / 256, MROWS / 128), 512, GEMM_DSMEM>>>(
        ath, atl, woh, wol, bo, out, nullptr, nullptr, 1.0f, MROWS, HID_, HID_, 0);
}

// round 14
// speedup vs baseline: 1.0983x; 1.0983x over previous
#include <cuda_runtime.h>
#include <cuda_bf16.h>
#include <cstdint>
#include <math.h>

#define B_     2
#define L_     2048
#define HID_   4096
#define NHEAD_ 32
#define NKV_   8
#define HDIM_  128
#define MROWS  (B_*L_)          // 4096
#define KVW    (2*NKV_*HDIM_)   // 2048
#define VW     (NKV_*HDIM_)     // 1024

// ------------------------- device scratch (no allocs) -----------------------
__device__ __align__(256) float g_v  [(size_t)MROWS * VW];   // V fp32 (16 MB)

__device__ __align__(256) __nv_bfloat16 g_qin_h [(size_t)MROWS * HID_];
__device__ __align__(256) __nv_bfloat16 g_qin_l [(size_t)MROWS * HID_];
__device__ __align__(256) __nv_bfloat16 g_kvin_h[(size_t)MROWS * HID_];
__device__ __align__(256) __nv_bfloat16 g_kvin_l[(size_t)MROWS * HID_];
__device__ __align__(256) __nv_bfloat16 g_att_h [(size_t)MROWS * HID_];
__device__ __align__(256) __nv_bfloat16 g_att_l [(size_t)MROWS * HID_];
__device__ __align__(256) __nv_bfloat16 g_wqt_h [(size_t)HID_ * HID_];
__device__ __align__(256) __nv_bfloat16 g_wqt_l [(size_t)HID_ * HID_];
__device__ __align__(256) __nv_bfloat16 g_wkvt_h[(size_t)KVW  * HID_];
__device__ __align__(256) __nv_bfloat16 g_wkvt_l[(size_t)KVW  * HID_];
__device__ __align__(256) __nv_bfloat16 g_wot_h [(size_t)HID_ * HID_];
__device__ __align__(256) __nv_bfloat16 g_wot_l [(size_t)HID_ * HID_];
// attention operands (bf16 hi/lo)
__device__ __align__(256) __nv_bfloat16 g_aqh[(size_t)MROWS * HID_];  // scaled Q
__device__ __align__(256) __nv_bfloat16 g_aql[(size_t)MROWS * HID_];
__device__ __align__(256) __nv_bfloat16 g_kh [(size_t)B_*NKV_*L_*HDIM_]; // [b,kvh,l,d]
__device__ __align__(256) __nv_bfloat16 g_kl [(size_t)B_*NKV_*L_*HDIM_];
__device__ __align__(256) __nv_bfloat16 g_vth[(size_t)B_*NKV_*HDIM_*L_]; // [b,kvh,d,l]
__device__ __align__(256) __nv_bfloat16 g_vtl[(size_t)B_*NKV_*HDIM_*L_];

// ------------------------------ PTX helpers ---------------------------------
__device__ __forceinline__ uint32_t smem_u32(const void* p) {
    uint32_t a;
    asm("{ .reg .u64 t; cvta.to.shared.u64 t, %1; cvt.u32.u64 %0, t; }"
        : "=r"(a) : "l"(p));
    return a;
}

__device__ __forceinline__ void ldsm4(uint32_t* r, uint32_t addr) {
    asm volatile("ldmatrix.sync.aligned.m8n8.x4.shared.b16 {%0,%1,%2,%3}, [%4];"
                 : "=r"(r[0]), "=r"(r[1]), "=r"(r[2]), "=r"(r[3]) : "r"(addr));
}

__device__ __forceinline__ void mma16816(float* d, const uint32_t* a,
                                         const uint32_t* b) {
    asm volatile(
        "mma.sync.aligned.m16n8k16.row.col.f32.bf16.bf16.f32 "
        "{%0,%1,%2,%3}, {%4,%5,%6,%7}, {%8,%9}, {%0,%1,%2,%3};"
        : "+f"(d[0]), "+f"(d[1]), "+f"(d[2]), "+f"(d[3])
        : "r"(a[0]), "r"(a[1]), "r"(a[2]), "r"(a[3]), "r"(b[0]), "r"(b[1]));
}

#define CP16(saddr, gaddr) \
    asm volatile("cp.async.cg.shared.global [%0], [%1], 16;" \
                 :: "r"(saddr), "l"(gaddr) : "memory")
#define CP_COMMIT()  asm volatile("cp.async.commit_group;" ::: "memory")
#define CP_WAIT0()   asm volatile("cp.async.wait_group 0;" ::: "memory")
#define CP_WAIT2()   asm volatile("cp.async.wait_group 2;" ::: "memory")

__device__ __forceinline__ unsigned short f2bf_bits(float x) {
    __nv_bfloat16 h = __float2bfloat16(x);
    return *(unsigned short*)&h;
}
__device__ __forceinline__ float bf_bits2f(unsigned short b) {
    __nv_bfloat16 h = *(__nv_bfloat16*)&b;
    return __bfloat162float(h);
}
__device__ __forceinline__ uint32_t pack_hi(float a, float b) {
    return (uint32_t)f2bf_bits(a) | ((uint32_t)f2bf_bits(b) << 16);
}
__device__ __forceinline__ uint32_t pack_lo(float a, float b) {
    unsigned short ha = f2bf_bits(a), hb = f2bf_bits(b);
    return (uint32_t)f2bf_bits(a - bf_bits2f(ha))
         | ((uint32_t)f2bf_bits(b - bf_bits2f(hb)) << 16);
}

// ---------------------------- conversion kernels ----------------------------
__global__ __launch_bounds__(256) void split_k(const float* __restrict__ in,
                                               __nv_bfloat16* __restrict__ hi,
                                               __nv_bfloat16* __restrict__ lo,
                                               int n4, float scale)
{
    int i = blockIdx.x * 256 + threadIdx.x;
    if (i >= n4) return;
    float4 v = ((const float4*)in)[i];
    v.x *= scale; v.y *= scale; v.z *= scale; v.w *= scale;
    ((uint2*)hi)[i] = make_uint2(pack_hi(v.x, v.y), pack_hi(v.z, v.w));
    ((uint2*)lo)[i] = make_uint2(pack_lo(v.x, v.y), pack_lo(v.z, v.w));
}

// W[K][N] fp32 -> Wt_hi/lo[N][K] bf16 (tiled transpose)
__global__ __launch_bounds__(256) void tsplit_k(const float* __restrict__ W,
                                                __nv_bfloat16* __restrict__ Th,
                                                __nv_bfloat16* __restrict__ Tl,
                                                int K, int N)
{
    __shared__ float t[32][33];
    int tx = threadIdx.x, ty = threadIdx.y;   // 32 x 8
    int n0 = blockIdx.x * 32, k0 = blockIdx.y * 32;
#pragma unroll
    for (int i = 0; i < 4; i++)
        t[ty + 8 * i][tx] = W[(size_t)(k0 + ty + 8 * i) * N + n0 + tx];
    __syncthreads();
#pragma unroll
    for (int i = 0; i < 4; i++) {
        float v = t[tx][ty + 8 * i];
        unsigned short h = f2bf_bits(v);
        unsigned short l = f2bf_bits(v - bf_bits2f(h));
        size_t o = (size_t)(n0 + ty + 8 * i) * K + k0 + tx;
        Th[o] = *(__nv_bfloat16*)&h; Tl[o] = *(__nv_bfloat16*)&l;
    }
}

// V prep: g_v fp32 [b*L+l][kvh*128+d] -> vth/vtl [b,kvh,d,l] bf16 (transpose)
__global__ __launch_bounds__(256) void vtprep_k(const float* __restrict__ V,
                                                __nv_bfloat16* __restrict__ Vh,
                                                __nv_bfloat16* __restrict__ Vl)
{
    __shared__ float t[32][33];
    int tx = threadIdx.x, ty = threadIdx.y;
    int l0 = blockIdx.x * 32, d0 = blockIdx.y * 32;
    int bk = blockIdx.z;
    int b = bk >> 3, kvh = bk & 7;
#pragma unroll
    for (int i = 0; i < 4; i++)
        t[ty + 8 * i][tx] = V[(size_t)(b * L_ + l0 + ty + 8 * i) * VW
                              + kvh * HDIM_ + d0 + tx];
    __syncthreads();
#pragma unroll
    for (int i = 0; i < 4; i++) {
        float v = t[tx][ty + 8 * i];
        unsigned short h = f2bf_bits(v);
        unsigned short l = f2bf_bits(v - bf_bits2f(h));
        size_t o = ((size_t)bk * HDIM_ + d0 + ty + 8 * i) * L_ + l0 + tx;
        Vh[o] = *(__nv_bfloat16*)&h; Vl[o] = *(__nv_bfloat16*)&l;
    }
}

// ------ HMMA GEMM: 128x128 tile, 256 thr, 4-stage K16 cp.async, 2 CTAs/SM ---
// Always-commit / wait_group 2 -> prefetch distance 3 half-iters, copy hidden.
#define SST     24                      // bf16 row stride (48 B, conflict-free)
#define TILE16B 6144u                   // 128*24*2
#define STAGE4B (4u * TILE16B)          // 24576 B (Ah,Al,Bh,Bl)
#define GEMM_DSMEM (4 * (int)STAGE4B)   // 98304 B

__global__ __launch_bounds__(256, 2) void hgemm_db_k(
    const __nv_bfloat16* __restrict__ Ah, const __nv_bfloat16* __restrict__ Al,
    const __nv_bfloat16* __restrict__ Bh, const __nv_bfloat16* __restrict__ Bl,
    const float* __restrict__ bias,
    float* __restrict__ C,
    __nv_bfloat16* __restrict__ Ch, __nv_bfloat16* __restrict__ Cl,
    float oscale, int M, int N, int K, int mode)
{
    extern __shared__ __nv_bfloat16 dynsm[];
    const uint32_t sbase = smem_u32(dynsm);

    const int tid  = threadIdx.x;
    const int wid  = tid >> 5, lane = tid & 31;
    const int gr   = lane >> 2, tg = lane & 3;
    const int wm   = (wid & 1) * 64;
    const int wn   = (wid >> 1) * 32;
    const int row0 = blockIdx.y * 128, col0 = blockIdx.x * 128;
    const int q    = lane >> 3, rr = lane & 7;

    float acc[4][4][4];
#pragma unroll
    for (int mt = 0; mt < 4; mt++)
#pragma unroll
        for (int nt = 0; nt < 4; nt++)
#pragma unroll
            for (int e = 0; e < 4; e++) acc[mt][nt][e] = 0.f;

    // loader: 128 rows x 16 cols per tile; 1 CP16 per thread per tile
    const int arow = tid >> 1, ach = (tid & 1) * 8;
    const uint32_t soA = (uint32_t)(arow * SST + ach) * 2;
    const __nv_bfloat16* pAh = Ah + (size_t)row0 * K;
    const __nv_bfloat16* pAl = Al + (size_t)row0 * K;
    const __nv_bfloat16* pBh = Bh + (size_t)col0 * K;
    const __nv_bfloat16* pBl = Bl + (size_t)col0 * K;

    const int niter = K >> 4;   // K/16

    auto issue = [&](uint32_t bb, int it) {
        const int kt = it << 4;
        CP16(bb + soA,                pAh + (size_t)arow * K + kt + ach);
        CP16(bb + TILE16B + soA,      pAl + (size_t)arow * K + kt + ach);
        CP16(bb + 2 * TILE16B + soA,  pBh + (size_t)arow * K + kt + ach);
        CP16(bb + 3 * TILE16B + soA,  pBl + (size_t)arow * K + kt + ach);
    };

    issue(sbase, 0);               CP_COMMIT();
    issue(sbase + STAGE4B, 1);     CP_COMMIT();
    issue(sbase + 2 * STAGE4B, 2); CP_COMMIT();

    for (int it = 0; it < niter; ++it) {
        const uint32_t st = sbase + (uint32_t)(it & 3) * STAGE4B;
        CP_WAIT2();            // group carrying stage it complete
        __syncthreads();       // all warps done reading stage (it-1)&3
        if (it + 3 < niter) issue(sbase + (uint32_t)((it + 3) & 3) * STAGE4B, it + 3);
        CP_COMMIT();           // one group per iteration (possibly empty)

        const uint32_t aAh = st;
        const uint32_t aAl = st + TILE16B;
        const uint32_t aBh = st + 2 * TILE16B;
        const uint32_t aBl = st + 3 * TILE16B;

        // B fragments resident (16 regs)
        uint32_t fBh0[4], fBh1[4], fBl0[4], fBl1[4];
        {
            uint32_t offb0 = (uint32_t)((wn + (q >> 1) * 8 + rr) * (SST * 2)
                                        + ((q & 1) * 8) * 2);
            uint32_t offb1 = offb0 + 16u * (SST * 2);
            ldsm4(fBh0, aBh + offb0);
            ldsm4(fBh1, aBh + offb1);
            ldsm4(fBl0, aBl + offb0);
            ldsm4(fBl1, aBl + offb1);
        }
#pragma unroll
        for (int mt = 0; mt < 4; ++mt) {
            uint32_t offa = (uint32_t)((wm + mt * 16 + (q & 1) * 8 + rr) * (SST * 2)
                                       + ((q >> 1) * 8) * 2);
            uint32_t fA[4];
            ldsm4(fA, aAh + offa);
            mma16816(acc[mt][0], fA, &fBh0[0]);
            mma16816(acc[mt][1], fA, &fBh0[2]);
            mma16816(acc[mt][2], fA, &fBh1[0]);
            mma16816(acc[mt][3], fA, &fBh1[2]);
            mma16816(acc[mt][0], fA, &fBl0[0]);
            mma16816(acc[mt][1], fA, &fBl0[2]);
            mma16816(acc[mt][2], fA, &fBl1[0]);
            mma16816(acc[mt][3], fA, &fBl1[2]);
            uint32_t fA2[4];
            ldsm4(fA2, aAl + offa);
            mma16816(acc[mt][0], fA2, &fBh0[0]);
            mma16816(acc[mt][1], fA2, &fBh0[2]);
            mma16816(acc[mt][2], fA2, &fBh1[0]);
            mma16816(acc[mt][3], fA2, &fBh1[2]);
        }
    }

    // ---- epilogue ----
    const bool kv_kpart = (mode == 2) && (col0 < VW);
    if (mode == 1 || kv_kpart) {
#pragma unroll
        for (int mt = 0; mt < 4; ++mt) {
#pragma unroll
            for (int nt = 0; nt < 4; ++nt) {
                int r = row0 + wm + mt * 16 + gr;
                int c = col0 + wn + nt * 8 + tg * 2;
                float b0 = bias[c], b1 = bias[c + 1];
                float v0 = (acc[mt][nt][0] + b0) * oscale;
                float v1 = (acc[mt][nt][1] + b1) * oscale;
                float v2 = (acc[mt][nt][2] + b0) * oscale;
                float v3 = (acc[mt][nt][3] + b1) * oscale;
                size_t o0, o1;
                if (kv_kpart) {
                    int bb = r >> 11, ll = r & (L_ - 1);
                    int kvhh = c >> 7, d = c & (HDIM_ - 1);
                    o0 = ((size_t)(bb * NKV_ + kvhh) * L_ + ll) * HDIM_ + d;
                    o1 = o0 + (size_t)8 * HDIM_;
                } else {
                    o0 = (size_t)r * N + c;
                    o1 = (size_t)(r + 8) * N + c;
                }
                *(uint32_t*)(Ch + o0) = pack_hi(v0, v1);
                *(uint32_t*)(Cl + o0) = pack_lo(v0, v1);
                *(uint32_t*)(Ch + o1) = pack_hi(v2, v3);
                *(uint32_t*)(Cl + o1) = pack_lo(v2, v3);
            }
        }
    } else {
        const int cw    = (mode == 2) ? VW : N;
        const int cbase = (mode == 2) ? (col0 - VW) : col0;
#pragma unroll
        for (int mt = 0; mt < 4; ++mt) {
#pragma unroll
            for (int nt = 0; nt < 4; ++nt) {
                int r = row0 + wm + mt * 16 + gr;
                int c = col0 + wn + nt * 8 + tg * 2;
                float b0 = bias[c], b1 = bias[c + 1];
                int cc = cbase + wn + nt * 8 + tg * 2;
                float2 v0 = make_float2(acc[mt][nt][0] + b0, acc[mt][nt][1] + b1);
                float2 v1 = make_float2(acc[mt][nt][2] + b0, acc[mt][nt][3] + b1);
                *(float2*)(C + (size_t)r * cw + cc) = v0;
                *(float2*)(C + (size_t)(r + 8) * cw + cc) = v1;
            }
        }
    }
}

// ---------------------------------------------------------------------------
// Tensor-core flash attention — validated R12 version (double-buffered V,
// mid-iteration K refill, register-resident Q).
// ---------------------------------------------------------------------------
#define QSTR 136
#define VSTR 72
#define KPAIR_B  (2u * 64 * QSTR * 2)
#define VPAIR_B  (2u * 128 * VSTR * 2)
#define ATT_SMEM ((int)(KPAIR_B + 2 * VPAIR_B))   // 108544 B

__global__ __launch_bounds__(128) void attn_tc_k(
    const __nv_bfloat16* __restrict__ Qh, const __nv_bfloat16* __restrict__ Ql,
    const __nv_bfloat16* __restrict__ Kh, const __nv_bfloat16* __restrict__ Kl,
    const __nv_bfloat16* __restrict__ Vh, const __nv_bfloat16* __restrict__ Vl,
    __nv_bfloat16* __restrict__ Oh, __nv_bfloat16* __restrict__ Ol)
{
    extern __shared__ __nv_bfloat16 smem_bf[];
    const uint32_t sb  = smem_u32(smem_bf);
    const uint32_t aKh = sb;
    const uint32_t aKl = aKh + 64 * QSTR * 2;
    const uint32_t aV0 = aKl + 64 * QSTR * 2;
    const uint32_t aV1 = aV0 + VPAIR_B;

    const int b = blockIdx.z, head = blockIdx.y, qt = blockIdx.x;
    const int kvh = head >> 2;
    const int tid = threadIdx.x;
    const int wid = tid >> 5, lane = tid & 31;
    const int q = lane >> 3, rr = lane & 7;
    const int gr = lane >> 2, tg = lane & 3;

    const __nv_bfloat16* kbh = Kh + (size_t)(b * NKV_ + kvh) * L_ * HDIM_;
    const __nv_bfloat16* kbl = Kl + (size_t)(b * NKV_ + kvh) * L_ * HDIM_;
    const __nv_bfloat16* vbh = Vh + (size_t)(b * NKV_ + kvh) * HDIM_ * L_;
    const __nv_bfloat16* vbl = Vl + (size_t)(b * NKV_ + kvh) * HDIM_ * L_;

    auto issueK = [&](int t) {
#pragma unroll
        for (int i = 0; i < 8; i++) {
            int idx = tid + i * 128;
            int row = idx >> 4, ch = idx & 15;
            uint32_t so = (uint32_t)(row * QSTR + ch * 8) * 2;
            CP16(aKh + so, kbh + (size_t)(t * 64 + row) * HDIM_ + ch * 8);
            CP16(aKl + so, kbl + (size_t)(t * 64 + row) * HDIM_ + ch * 8);
        }
    };
    auto issueV = [&](int t, uint32_t vb) {
#pragma unroll
        for (int i = 0; i < 8; i++) {
            int idx = tid + i * 128;
            int vrow = idx >> 3, vch = idx & 7;
            uint32_t so = (uint32_t)(vrow * VSTR + vch * 8) * 2;
            CP16(vb + so,                   vbh + (size_t)vrow * L_ + t * 64 + vch * 8);
            CP16(vb + 128 * VSTR * 2 + so,  vbl + (size_t)vrow * L_ + t * 64 + vch * 8);
        }
    };

    {
        const __nv_bfloat16* qbh = Qh + (size_t)(b * L_ + qt * 64) * HID_ + head * HDIM_;
        const __nv_bfloat16* qbl = Ql + (size_t)(b * L_ + qt * 64) * HID_ + head * HDIM_;
#pragma unroll
        for (int i = 0; i < 8; i++) {
            int idx = tid + i * 128;
            int row = idx >> 4, ch = idx & 15;
            uint32_t so = (uint32_t)(row * QSTR + ch * 8) * 2;
            CP16(aKh + so, qbh + (size_t)row * HID_ + ch * 8);
            CP16(aKl + so, qbl + (size_t)row * HID_ + ch * 8);
        }
        CP_COMMIT(); CP_WAIT0();
    }
    __syncthreads();
    uint32_t fQh[8][4], fQl[8][4];
#pragma unroll
    for (int ks = 0; ks < 8; ++ks) {
        uint32_t aoff = (uint32_t)((wid * 16 + (q & 1) * 8 + rr) * (QSTR * 2)
                                   + (ks * 16 + (q >> 1) * 8) * 2);
        ldsm4(fQh[ks], aKh + aoff);
        ldsm4(fQl[ks], aKl + aoff);
    }
    __syncthreads();

    issueK(0); issueV(0, aV0); CP_COMMIT();

    float oacc[16][4];
#pragma unroll
    for (int nt = 0; nt < 16; nt++)
#pragma unroll
        for (int e = 0; e < 4; e++) oacc[nt][e] = 0.f;
    float m0 = -1e30f, m1 = -1e30f, l0 = 0.f, l1 = 0.f;

    const int NT = L_ / 64;
    for (int t = 0; t < NT; ++t) {
        const uint32_t vcur = (t & 1) ? aV1 : aV0;
        const uint32_t vnxt = (t & 1) ? aV0 : aV1;

        CP_WAIT0();
        __syncthreads();

        if (t + 1 < NT) { issueV(t + 1, vnxt); CP_COMMIT(); }

        float sacc[8][4];
#pragma unroll
        for (int nt = 0; nt < 8; nt++)
#pragma unroll
            for (int e = 0; e < 4; e++) sacc[nt][e] = 0.f;

#pragma unroll
        for (int ks = 0; ks < 8; ++ks) {
            uint32_t fKh[4][4], fKl[4][4];
#pragma unroll
            for (int np = 0; np < 4; ++np) {
                uint32_t boff = (uint32_t)((np * 16 + (q >> 1) * 8 + rr) * (QSTR * 2)
                                           + (ks * 16 + (q & 1) * 8) * 2);
                ldsm4(fKh[np], aKh + boff);
                ldsm4(fKl[np], aKl + boff);
            }
#pragma unroll
            for (int nt = 0; nt < 8; ++nt) {
                const uint32_t* bh = &fKh[nt >> 1][(nt & 1) * 2];
                const uint32_t* bl = &fKl[nt >> 1][(nt & 1) * 2];
                mma16816(sacc[nt], fQh[ks], bh);
                mma16816(sacc[nt], fQl[ks], bh);
                mma16816(sacc[nt], fQh[ks], bl);
            }
        }
        __syncthreads();
        if (t + 1 < NT) { issueK(t + 1); CP_COMMIT(); }

        float rmax0 = -1e30f, rmax1 = -1e30f;
#pragma unroll
        for (int nt = 0; nt < 8; ++nt) {
            rmax0 = fmaxf(rmax0, fmaxf(sacc[nt][0], sacc[nt][1]));
            rmax1 = fmaxf(rmax1, fmaxf(sacc[nt][2], sacc[nt][3]));
        }
        rmax0 = fmaxf(rmax0, __shfl_xor_sync(0xffffffffu, rmax0, 1));
        rmax0 = fmaxf(rmax0, __shfl_xor_sync(0xffffffffu, rmax0, 2));
        rmax1 = fmaxf(rmax1, __shfl_xor_sync(0xffffffffu, rmax1, 1));
        rmax1 = fmaxf(rmax1, __shfl_xor_sync(0xffffffffu, rmax1, 2));
        float mn0 = fmaxf(m0, rmax0), mn1 = fmaxf(m1, rmax1);
        float fact0 = __expf(m0 - mn0), fact1 = __expf(m1 - mn1);
        m0 = mn0; m1 = mn1;
        float sum0 = 0.f, sum1 = 0.f;
#pragma unroll
        for (int nt = 0; nt < 8; ++nt) {
            sacc[nt][0] = __expf(sacc[nt][0] - mn0); sum0 += sacc[nt][0];
            sacc[nt][1] = __expf(sacc[nt][1] - mn0); sum0 += sacc[nt][1];
            sacc[nt][2] = __expf(sacc[nt][2] - mn1); sum1 += sacc[nt][2];
            sacc[nt][3] = __expf(sacc[nt][3] - mn1); sum1 += sacc[nt][3];
        }
        sum0 += __shfl_xor_sync(0xffffffffu, sum0, 1);
        sum0 += __shfl_xor_sync(0xffffffffu, sum0, 2);
        sum1 += __shfl_xor_sync(0xffffffffu, sum1, 1);
        sum1 += __shfl_xor_sync(0xffffffffu, sum1, 2);
        l0 = l0 * fact0 + sum0;
        l1 = l1 * fact1 + sum1;
#pragma unroll
        for (int nt = 0; nt < 16; ++nt) {
            oacc[nt][0] *= fact0; oacc[nt][1] *= fact0;
            oacc[nt][2] *= fact1; oacc[nt][3] *= fact1;
        }

        const uint32_t aVhc = vcur, aVlc = vcur + 128 * VSTR * 2;
#pragma unroll
        for (int j = 0; j < 4; ++j) {
            uint32_t aPh[4], aPl[4];
#pragma unroll
            for (int hlf = 0; hlf < 2; ++hlf) {
                const float* p = sacc[2 * j + hlf];
                aPh[2 * hlf]     = pack_hi(p[0], p[1]);
                aPh[2 * hlf + 1] = pack_hi(p[2], p[3]);
                aPl[2 * hlf]     = pack_lo(p[0], p[1]);
                aPl[2 * hlf + 1] = pack_lo(p[2], p[3]);
            }
#pragma unroll
            for (int nn = 0; nn < 8; ++nn) {
                uint32_t fVh[4], fVl[4];
                uint32_t voff = (uint32_t)((nn * 16 + (q >> 1) * 8 + rr) * (VSTR * 2)
                                           + (j * 16 + (q & 1) * 8) * 2);
                ldsm4(fVh, aVhc + voff);
                ldsm4(fVl, aVlc + voff);
                mma16816(oacc[2 * nn], aPh, &fVh[0]);
                mma16816(oacc[2 * nn], aPl, &fVh[0]);
                mma16816(oacc[2 * nn], aPh, &fVl[0]);
                mma16816(oacc[2 * nn + 1], aPh, &fVh[2]);
                mma16816(oacc[2 * nn + 1], aPl, &fVh[2]);
                mma16816(oacc[2 * nn + 1], aPh, &fVl[2]);
            }
        }
    }

    float inv0 = 1.0f / l0, inv1 = 1.0f / l1;
    const int row0g = b * L_ + qt * 64 + wid * 16 + gr;
    __nv_bfloat16* oh0 = Oh + (size_t)row0g * HID_ + head * HDIM_;
    __nv_bfloat16* ol0 = Ol + (size_t)row0g * HID_ + head * HDIM_;
    __nv_bfloat16* oh1 = oh0 + (size_t)8 * HID_;
    __nv_bfloat16* ol1 = ol0 + (size_t)8 * HID_;
#pragma unroll
    for (int nt = 0; nt < 16; ++nt) {
        int col = nt * 8 + tg * 2;
        float v0 = oacc[nt][0] * inv0, v1 = oacc[nt][1] * inv0;
        float v2 = oacc[nt][2] * inv1, v3 = oacc[nt][3] * inv1;
        *(uint32_t*)(oh0 + col) = pack_hi(v0, v1);
        *(uint32_t*)(ol0 + col) = pack_lo(v0, v1);
        *(uint32_t*)(oh1 + col) = pack_hi(v2, v3);
        *(uint32_t*)(ol1 + col) = pack_lo(v2, v3);
    }
}

// ---------------------------------------------------------------------------
extern "C" void kernel_launch(void* const* d_in, const int* in_sizes, int n_in,
                              void* d_out, int out_size)
{
    const float* query = (const float*)d_in[0];
    const float* kv    = (const float*)d_in[1];
    const float* Wq    = (const float*)d_in[2];
    const float* bq    = (const float*)d_in[3];
    const float* Wkv   = (const float*)d_in[4];
    const float* bkv   = (const float*)d_in[5];
    const float* Wo    = (const float*)d_in[6];
    const float* bo    = (const float*)d_in[7];
    float* out = (float*)d_out;

    float* pv = nullptr;
    cudaGetSymbolAddress((void**)&pv, g_v);
    __nv_bfloat16 *qh, *ql, *kvh, *kvl, *ath, *atl;
    __nv_bfloat16 *wqh, *wql, *wkh, *wkl, *woh, *wol;
    __nv_bfloat16 *aqh, *aql, *akh, *akl, *avh, *avl;
    cudaGetSymbolAddress((void**)&qh,  g_qin_h);  cudaGetSymbolAddress((void**)&ql,  g_qin_l);
    cudaGetSymbolAddress((void**)&kvh, g_kvin_h); cudaGetSymbolAddress((void**)&kvl, g_kvin_l);
    cudaGetSymbolAddress((void**)&ath, g_att_h);  cudaGetSymbolAddress((void**)&atl, g_att_l);
    cudaGetSymbolAddress((void**)&wqh, g_wqt_h);  cudaGetSymbolAddress((void**)&wql, g_wqt_l);
    cudaGetSymbolAddress((void**)&wkh, g_wkvt_h); cudaGetSymbolAddress((void**)&wkl, g_wkvt_l);
    cudaGetSymbolAddress((void**)&woh, g_wot_h);  cudaGetSymbolAddress((void**)&wol, g_wot_l);
    cudaGetSymbolAddress((void**)&aqh, g_aqh);    cudaGetSymbolAddress((void**)&aql, g_aql);
    cudaGetSymbolAddress((void**)&akh, g_kh);     cudaGetSymbolAddress((void**)&akl, g_kl);
    cudaGetSymbolAddress((void**)&avh, g_vth);    cudaGetSymbolAddress((void**)&avl, g_vtl);

    cudaFuncSetAttribute(attn_tc_k, cudaFuncAttributeMaxDynamicSharedMemorySize,
                         ATT_SMEM);
    cudaFuncSetAttribute(hgemm_db_k, cudaFuncAttributeMaxDynamicSharedMemorySize,
                         GEMM_DSMEM);

    const int n_act4 = (MROWS * HID_) / 4;
    const float qscale = 0.08838834764831845f;   // 1/sqrt(128)

    split_k<<<(n_act4 + 255) / 256, 256>>>(query, qh, ql, n_act4, 1.0f);            // 0
    tsplit_k<<<dim3(HID_ / 32, HID_ / 32), dim3(32, 8)>>>(Wq, wqh, wql, HID_, HID_); // 1
    split_k<<<(n_act4 + 255) / 256, 256>>>(kv, kvh, kvl, n_act4, 1.0f);             // 2
    // 3: Q projection (ncu capture slot)
    hgemm_db_k<<<dim3(HID_ / 128, MROWS / 128), 256, GEMM_DSMEM>>>(
        qh, ql, wqh, wql, bq, nullptr, aqh, aql, qscale, MROWS, HID_, HID_, 1);
    tsplit_k<<<dim3(KVW / 32, HID_ / 32), dim3(32, 8)>>>(Wkv, wkh, wkl, HID_, KVW); // 4
    // 5: KV projection -> K [b,kvh,l,d] bf16 hi/lo; V fp32
    hgemm_db_k<<<dim3(KVW / 128, MROWS / 128), 256, GEMM_DSMEM>>>(
        kvh, kvl, wkh, wkl, bkv, pv, akh, akl, 1.0f, MROWS, KVW, HID_, 2);
    tsplit_k<<<dim3(HID_ / 32, HID_ / 32), dim3(32, 8)>>>(Wo, woh, wol, HID_, HID_); // 6
    vtprep_k<<<dim3(L_ / 32, HDIM_ / 32, B_ * NKV_), dim3(32, 8)>>>(pv, avh, avl);   // 7
    // 8: tensor-core attention
    attn_tc_k<<<dim3(L_ / 64, NHEAD_, B_), 128, ATT_SMEM>>>(
        aqh, aql, akh, akl, avh, avl, ath, atl);
    // 9: O projection -> fp32 out
    hgemm_db_k<<<dim3(HID_ / 128, MROWS / 128), 256, GEMM_DSMEM>>>(
        ath, atl, woh, wol, bo, out, nullptr, nullptr, 1.0f, MROWS, HID_, HID_, 0);
}

// round 15
// speedup vs baseline: 1.1311x; 1.0299x over previous
#include <cuda_runtime.h>
#include <cuda_bf16.h>
#include <cstdint>
#include <math.h>

#define B_     2
#define L_     2048
#define HID_   4096
#define NHEAD_ 32
#define NKV_   8
#define HDIM_  128
#define MROWS  (B_*L_)          // 4096
#define KVW    (2*NKV_*HDIM_)   // 2048
#define VW     (NKV_*HDIM_)     // 1024

// ------------------------- device scratch (no allocs) -----------------------
__device__ __align__(256) float g_v  [(size_t)MROWS * VW];   // V fp32 (16 MB)

__device__ __align__(256) __nv_bfloat16 g_qin_h [(size_t)MROWS * HID_];
__device__ __align__(256) __nv_bfloat16 g_qin_l [(size_t)MROWS * HID_];
__device__ __align__(256) __nv_bfloat16 g_kvin_h[(size_t)MROWS * HID_];
__device__ __align__(256) __nv_bfloat16 g_kvin_l[(size_t)MROWS * HID_];
__device__ __align__(256) __nv_bfloat16 g_att_h [(size_t)MROWS * HID_];
__device__ __align__(256) __nv_bfloat16 g_att_l [(size_t)MROWS * HID_];
__device__ __align__(256) __nv_bfloat16 g_wqt_h [(size_t)HID_ * HID_];
__device__ __align__(256) __nv_bfloat16 g_wqt_l [(size_t)HID_ * HID_];
__device__ __align__(256) __nv_bfloat16 g_wkvt_h[(size_t)KVW  * HID_];
__device__ __align__(256) __nv_bfloat16 g_wkvt_l[(size_t)KVW  * HID_];
__device__ __align__(256) __nv_bfloat16 g_wot_h [(size_t)HID_ * HID_];
__device__ __align__(256) __nv_bfloat16 g_wot_l [(size_t)HID_ * HID_];
// attention operands (bf16 hi/lo)
__device__ __align__(256) __nv_bfloat16 g_aqh[(size_t)MROWS * HID_];  // scaled Q
__device__ __align__(256) __nv_bfloat16 g_aql[(size_t)MROWS * HID_];
__device__ __align__(256) __nv_bfloat16 g_kh [(size_t)B_*NKV_*L_*HDIM_]; // [b,kvh,l,d]
__device__ __align__(256) __nv_bfloat16 g_kl [(size_t)B_*NKV_*L_*HDIM_];
__device__ __align__(256) __nv_bfloat16 g_vth[(size_t)B_*NKV_*HDIM_*L_]; // [b,kvh,d,l]
__device__ __align__(256) __nv_bfloat16 g_vtl[(size_t)B_*NKV_*HDIM_*L_];

// ------------------------------ PTX helpers ---------------------------------
__device__ __forceinline__ uint32_t smem_u32(const void* p) {
    uint32_t a;
    asm("{ .reg .u64 t; cvta.to.shared.u64 t, %1; cvt.u32.u64 %0, t; }"
        : "=r"(a) : "l"(p));
    return a;
}

__device__ __forceinline__ void ldsm4(uint32_t* r, uint32_t addr) {
    asm volatile("ldmatrix.sync.aligned.m8n8.x4.shared.b16 {%0,%1,%2,%3}, [%4];"
                 : "=r"(r[0]), "=r"(r[1]), "=r"(r[2]), "=r"(r[3]) : "r"(addr));
}

__device__ __forceinline__ void mma16816(float* d, const uint32_t* a,
                                         const uint32_t* b) {
    asm volatile(
        "mma.sync.aligned.m16n8k16.row.col.f32.bf16.bf16.f32 "
        "{%0,%1,%2,%3}, {%4,%5,%6,%7}, {%8,%9}, {%0,%1,%2,%3};"
        : "+f"(d[0]), "+f"(d[1]), "+f"(d[2]), "+f"(d[3])
        : "r"(a[0]), "r"(a[1]), "r"(a[2]), "r"(a[3]), "r"(b[0]), "r"(b[1]));
}

#define CP16(saddr, gaddr) \
    asm volatile("cp.async.cg.shared.global [%0], [%1], 16;" \
                 :: "r"(saddr), "l"(gaddr) : "memory")
#define CP_COMMIT()  asm volatile("cp.async.commit_group;" ::: "memory")
#define CP_WAIT0()   asm volatile("cp.async.wait_group 0;" ::: "memory")

__device__ __forceinline__ unsigned short f2bf_bits(float x) {
    __nv_bfloat16 h = __float2bfloat16(x);
    return *(unsigned short*)&h;
}
__device__ __forceinline__ float bf_bits2f(unsigned short b) {
    __nv_bfloat16 h = *(__nv_bfloat16*)&b;
    return __bfloat162float(h);
}
__device__ __forceinline__ uint32_t pack_hi(float a, float b) {
    return (uint32_t)f2bf_bits(a) | ((uint32_t)f2bf_bits(b) << 16);
}
__device__ __forceinline__ uint32_t pack_lo(float a, float b) {
    unsigned short ha = f2bf_bits(a), hb = f2bf_bits(b);
    return (uint32_t)f2bf_bits(a - bf_bits2f(ha))
         | ((uint32_t)f2bf_bits(b - bf_bits2f(hb)) << 16);
}

// ---------------------------- fused prep kernels ----------------------------
// split2: query -> qh/ql and kv -> kvh/kvl in one launch
__global__ __launch_bounds__(256) void split2_k(
    const float* __restrict__ inA, __nv_bfloat16* __restrict__ hiA,
    __nv_bfloat16* __restrict__ loA,
    const float* __restrict__ inB, __nv_bfloat16* __restrict__ hiB,
    __nv_bfloat16* __restrict__ loB, int n4)
{
    int nb = (n4 + 255) >> 8;
    const float* in; __nv_bfloat16 *hi, *lo;
    int i;
    if (blockIdx.x < nb) {
        in = inA; hi = hiA; lo = loA;
        i = blockIdx.x * 256 + threadIdx.x;
    } else {
        in = inB; hi = hiB; lo = loB;
        i = (blockIdx.x - nb) * 256 + threadIdx.x;
    }
    if (i >= n4) return;
    float4 v = ((const float4*)in)[i];
    ((uint2*)hi)[i] = make_uint2(pack_hi(v.x, v.y), pack_hi(v.z, v.w));
    ((uint2*)lo)[i] = make_uint2(pack_lo(v.x, v.y), pack_lo(v.z, v.w));
}

// tsplit3: Wq/Wkv/Wo -> transposed bf16 hi/lo in one launch (K=4096 for all)
__global__ __launch_bounds__(256) void tsplit3_k(
    const float* __restrict__ Wq_, __nv_bfloat16* __restrict__ TqH,
    __nv_bfloat16* __restrict__ TqL,
    const float* __restrict__ Wk_, __nv_bfloat16* __restrict__ TkH,
    __nv_bfloat16* __restrict__ TkL,
    const float* __restrict__ Wo_, __nv_bfloat16* __restrict__ ToH,
    __nv_bfloat16* __restrict__ ToL)
{
    __shared__ float t[32][33];
    const int K = HID_;
    const float* W; __nv_bfloat16 *Th, *Tl;
    int N, bxl;
    int bx = blockIdx.x;
    if (bx < 128)      { W = Wq_; Th = TqH; Tl = TqL; N = HID_; bxl = bx; }
    else if (bx < 192) { W = Wk_; Th = TkH; Tl = TkL; N = KVW;  bxl = bx - 128; }
    else               { W = Wo_; Th = ToH; Tl = ToL; N = HID_; bxl = bx - 192; }

    int tx = threadIdx.x, ty = threadIdx.y;   // 32 x 8
    int n0 = bxl * 32, k0 = blockIdx.y * 32;
#pragma unroll
    for (int i = 0; i < 4; i++)
        t[ty + 8 * i][tx] = W[(size_t)(k0 + ty + 8 * i) * N + n0 + tx];
    __syncthreads();
#pragma unroll
    for (int i = 0; i < 4; i++) {
        float v = t[tx][ty + 8 * i];
        unsigned short h = f2bf_bits(v);
        unsigned short l = f2bf_bits(v - bf_bits2f(h));
        size_t o = (size_t)(n0 + ty + 8 * i) * K + k0 + tx;
        Th[o] = *(__nv_bfloat16*)&h; Tl[o] = *(__nv_bfloat16*)&l;
    }
}

// V prep: g_v fp32 [b*L+l][kvh*128+d] -> vth/vtl [b,kvh,d,l] bf16 (transpose)
__global__ __launch_bounds__(256) void vtprep_k(const float* __restrict__ V,
                                                __nv_bfloat16* __restrict__ Vh,
                                                __nv_bfloat16* __restrict__ Vl)
{
    __shared__ float t[32][33];
    int tx = threadIdx.x, ty = threadIdx.y;
    int l0 = blockIdx.x * 32, d0 = blockIdx.y * 32;
    int bk = blockIdx.z;
    int b = bk >> 3, kvh = bk & 7;
#pragma unroll
    for (int i = 0; i < 4; i++)
        t[ty + 8 * i][tx] = V[(size_t)(b * L_ + l0 + ty + 8 * i) * VW
                              + kvh * HDIM_ + d0 + tx];
    __syncthreads();
#pragma unroll
    for (int i = 0; i < 4; i++) {
        float v = t[tx][ty + 8 * i];
        unsigned short h = f2bf_bits(v);
        unsigned short l = f2bf_bits(v - bf_bits2f(h));
        size_t o = ((size_t)bk * HDIM_ + d0 + ty + 8 * i) * L_ + l0 + tx;
        Vh[o] = *(__nv_bfloat16*)&h; Vl[o] = *(__nv_bfloat16*)&l;
    }
}

// ---------------- HMMA GEMM, 2-stage cp.async, single-sync, 2 CTAs/SM -------
// (byte-identical to the validated Round-12 kernel)
#define SSTRIDE 40
#define TILEB   10240u
#define STAGEB  (4u * TILEB)           // 40960 B per stage
#define GEMM_DSMEM (2 * (int)STAGEB)   // 81920 B

__global__ __launch_bounds__(256, 2) void hgemm_db_k(
    const __nv_bfloat16* __restrict__ Ah, const __nv_bfloat16* __restrict__ Al,
    const __nv_bfloat16* __restrict__ Bh, const __nv_bfloat16* __restrict__ Bl,
    const float* __restrict__ bias,
    float* __restrict__ C,
    __nv_bfloat16* __restrict__ Ch, __nv_bfloat16* __restrict__ Cl,
    float oscale, int M, int N, int K, int mode)
{
    extern __shared__ __nv_bfloat16 dynsm[];
    const uint32_t sbase = smem_u32(dynsm);

    const int tid  = threadIdx.x;
    const int wid  = tid >> 5, lane = tid & 31;
    const int gr   = lane >> 2, tg = lane & 3;
    const int wm   = (wid & 1) * 64;
    const int wn   = (wid >> 1) * 32;
    const int row0 = blockIdx.y * 128, col0 = blockIdx.x * 128;
    const int q    = lane >> 3, rr = lane & 7;

    float acc[4][4][4];
#pragma unroll
    for (int mt = 0; mt < 4; mt++)
#pragma unroll
        for (int nt = 0; nt < 4; nt++)
#pragma unroll
            for (int e = 0; e < 4; e++) acc[mt][nt][e] = 0.f;

    const int lr0 = tid >> 2, lc0 = (tid & 3) * 8;
    const int lr1 = lr0 + 64;
    const uint32_t so0 = (uint32_t)(lr0 * SSTRIDE + lc0) * 2;
    const uint32_t so1 = (uint32_t)(lr1 * SSTRIDE + lc0) * 2;
    const __nv_bfloat16* pAh = Ah + (size_t)row0 * K;
    const __nv_bfloat16* pAl = Al + (size_t)row0 * K;
    const __nv_bfloat16* pBh = Bh + (size_t)col0 * K;
    const __nv_bfloat16* pBl = Bl + (size_t)col0 * K;

    const int niter = K >> 5;

    auto issue = [&](uint32_t bb, int it) {
        const int kt = it << 5;
        CP16(bb + so0,              pAh + (size_t)lr0 * K + kt + lc0);
        CP16(bb + so1,              pAh + (size_t)lr1 * K + kt + lc0);
        CP16(bb + TILEB + so0,      pAl + (size_t)lr0 * K + kt + lc0);
        CP16(bb + TILEB + so1,      pAl + (size_t)lr1 * K + kt + lc0);
        CP16(bb + 2 * TILEB + so0,  pBh + (size_t)lr0 * K + kt + lc0);
        CP16(bb + 2 * TILEB + so1,  pBh + (size_t)lr1 * K + kt + lc0);
        CP16(bb + 3 * TILEB + so0,  pBl + (size_t)lr0 * K + kt + lc0);
        CP16(bb + 3 * TILEB + so1,  pBl + (size_t)lr1 * K + kt + lc0);
    };

    issue(sbase, 0); CP_COMMIT();

    uint32_t s = 0;
    for (int it = 0; it < niter; ++it) {
        CP_WAIT0();
        __syncthreads();
        if (it + 1 < niter) { issue(sbase + (s ^ STAGEB), it + 1); CP_COMMIT(); }

        const uint32_t aAh = sbase + s;
        const uint32_t aAl = aAh + TILEB;
        const uint32_t aBh = aAh + 2 * TILEB;
        const uint32_t aBl = aAh + 3 * TILEB;

#pragma unroll
        for (int ks = 0; ks < 2; ++ks) {
            uint32_t fBh0[4], fBh1[4], fBl0[4], fBl1[4];
            {
                uint32_t offb0 = (uint32_t)((wn + (q >> 1) * 8 + rr) * (SSTRIDE * 2)
                                            + (ks * 16 + (q & 1) * 8) * 2);
                uint32_t offb1 = offb0 + 16u * (SSTRIDE * 2);
                ldsm4(fBh0, aBh + offb0);
                ldsm4(fBh1, aBh + offb1);
                ldsm4(fBl0, aBl + offb0);
                ldsm4(fBl1, aBl + offb1);
            }
#pragma unroll
            for (int mt = 0; mt < 4; ++mt) {
                uint32_t offa = (uint32_t)((wm + mt * 16 + (q & 1) * 8 + rr) * (SSTRIDE * 2)
                                           + (ks * 16 + (q >> 1) * 8) * 2);
                uint32_t fA[4];
                ldsm4(fA, aAh + offa);
                mma16816(acc[mt][0], fA, &fBh0[0]);
                mma16816(acc[mt][1], fA, &fBh0[2]);
                mma16816(acc[mt][2], fA, &fBh1[0]);
                mma16816(acc[mt][3], fA, &fBh1[2]);
                mma16816(acc[mt][0], fA, &fBl0[0]);
                mma16816(acc[mt][1], fA, &fBl0[2]);
                mma16816(acc[mt][2], fA, &fBl1[0]);
                mma16816(acc[mt][3], fA, &fBl1[2]);
                uint32_t fA2[4];
                ldsm4(fA2, aAl + offa);
                mma16816(acc[mt][0], fA2, &fBh0[0]);
                mma16816(acc[mt][1], fA2, &fBh0[2]);
                mma16816(acc[mt][2], fA2, &fBh1[0]);
                mma16816(acc[mt][3], fA2, &fBh1[2]);
            }
        }
        s ^= STAGEB;
    }

    // ---- epilogue ----
    const bool kv_kpart = (mode == 2) && (col0 < VW);
    if (mode == 1 || kv_kpart) {
#pragma unroll
        for (int mt = 0; mt < 4; ++mt) {
#pragma unroll
            for (int nt = 0; nt < 4; ++nt) {
                int r = row0 + wm + mt * 16 + gr;
                int c = col0 + wn + nt * 8 + tg * 2;
                float b0 = bias[c], b1 = bias[c + 1];
                float v0 = (acc[mt][nt][0] + b0) * oscale;
                float v1 = (acc[mt][nt][1] + b1) * oscale;
                float v2 = (acc[mt][nt][2] + b0) * oscale;
                float v3 = (acc[mt][nt][3] + b1) * oscale;
                size_t o0, o1;
                if (kv_kpart) {
                    int bb = r >> 11, ll = r & (L_ - 1);
                    int kvhh = c >> 7, d = c & (HDIM_ - 1);
                    o0 = ((size_t)(bb * NKV_ + kvhh) * L_ + ll) * HDIM_ + d;
                    o1 = o0 + (size_t)8 * HDIM_;
                } else {
                    o0 = (size_t)r * N + c;
                    o1 = (size_t)(r + 8) * N + c;
                }
                *(uint32_t*)(Ch + o0) = pack_hi(v0, v1);
                *(uint32_t*)(Cl + o0) = pack_lo(v0, v1);
                *(uint32_t*)(Ch + o1) = pack_hi(v2, v3);
                *(uint32_t*)(Cl + o1) = pack_lo(v2, v3);
            }
        }
    } else {
        const int cw    = (mode == 2) ? VW : N;
        const int cbase = (mode == 2) ? (col0 - VW) : col0;
#pragma unroll
        for (int mt = 0; mt < 4; ++mt) {
#pragma unroll
            for (int nt = 0; nt < 4; ++nt) {
                int r = row0 + wm + mt * 16 + gr;
                int c = col0 + wn + nt * 8 + tg * 2;
                float b0 = bias[c], b1 = bias[c + 1];
                int cc = cbase + wn + nt * 8 + tg * 2;
                float2 v0 = make_float2(acc[mt][nt][0] + b0, acc[mt][nt][1] + b1);
                float2 v1 = make_float2(acc[mt][nt][2] + b0, acc[mt][nt][3] + b1);
                *(float2*)(C + (size_t)r * cw + cc) = v0;
                *(float2*)(C + (size_t)(r + 8) * cw + cc) = v1;
            }
        }
    }
}

// ---------------------------------------------------------------------------
// Tensor-core flash attention — validated R12 version (double-buffered V,
// mid-iteration K refill, register-resident Q).
// ---------------------------------------------------------------------------
#define QSTR 136
#define VSTR 72
#define KPAIR_B  (2u * 64 * QSTR * 2)
#define VPAIR_B  (2u * 128 * VSTR * 2)
#define ATT_SMEM ((int)(KPAIR_B + 2 * VPAIR_B))   // 108544 B

__global__ __launch_bounds__(128) void attn_tc_k(
    const __nv_bfloat16* __restrict__ Qh, const __nv_bfloat16* __restrict__ Ql,
    const __nv_bfloat16* __restrict__ Kh, const __nv_bfloat16* __restrict__ Kl,
    const __nv_bfloat16* __restrict__ Vh, const __nv_bfloat16* __restrict__ Vl,
    __nv_bfloat16* __restrict__ Oh, __nv_bfloat16* __restrict__ Ol)
{
    extern __shared__ __nv_bfloat16 smem_bf[];
    const uint32_t sb  = smem_u32(smem_bf);
    const uint32_t aKh = sb;
    const uint32_t aKl = aKh + 64 * QSTR * 2;
    const uint32_t aV0 = aKl + 64 * QSTR * 2;
    const uint32_t aV1 = aV0 + VPAIR_B;

    const int b = blockIdx.z, head = blockIdx.y, qt = blockIdx.x;
    const int kvh = head >> 2;
    const int tid = threadIdx.x;
    const int wid = tid >> 5, lane = tid & 31;
    const int q = lane >> 3, rr = lane & 7;
    const int gr = lane >> 2, tg = lane & 3;

    const __nv_bfloat16* kbh = Kh + (size_t)(b * NKV_ + kvh) * L_ * HDIM_;
    const __nv_bfloat16* kbl = Kl + (size_t)(b * NKV_ + kvh) * L_ * HDIM_;
    const __nv_bfloat16* vbh = Vh + (size_t)(b * NKV_ + kvh) * HDIM_ * L_;
    const __nv_bfloat16* vbl = Vl + (size_t)(b * NKV_ + kvh) * HDIM_ * L_;

    auto issueK = [&](int t) {
#pragma unroll
        for (int i = 0; i < 8; i++) {
            int idx = tid + i * 128;
            int row = idx >> 4, ch = idx & 15;
            uint32_t so = (uint32_t)(row * QSTR + ch * 8) * 2;
            CP16(aKh + so, kbh + (size_t)(t * 64 + row) * HDIM_ + ch * 8);
            CP16(aKl + so, kbl + (size_t)(t * 64 + row) * HDIM_ + ch * 8);
        }
    };
    auto issueV = [&](int t, uint32_t vb) {
#pragma unroll
        for (int i = 0; i < 8; i++) {
            int idx = tid + i * 128;
            int vrow = idx >> 3, vch = idx & 7;
            uint32_t so = (uint32_t)(vrow * VSTR + vch * 8) * 2;
            CP16(vb + so,                   vbh + (size_t)vrow * L_ + t * 64 + vch * 8);
            CP16(vb + 128 * VSTR * 2 + so,  vbl + (size_t)vrow * L_ + t * 64 + vch * 8);
        }
    };

    {
        const __nv_bfloat16* qbh = Qh + (size_t)(b * L_ + qt * 64) * HID_ + head * HDIM_;
        const __nv_bfloat16* qbl = Ql + (size_t)(b * L_ + qt * 64) * HID_ + head * HDIM_;
#pragma unroll
        for (int i = 0; i < 8; i++) {
            int idx = tid + i * 128;
            int row = idx >> 4, ch = idx & 15;
            uint32_t so = (uint32_t)(row * QSTR + ch * 8) * 2;
            CP16(aKh + so, qbh + (size_t)row * HID_ + ch * 8);
            CP16(aKl + so, qbl + (size_t)row * HID_ + ch * 8);
        }
        CP_COMMIT(); CP_WAIT0();
    }
    __syncthreads();
    uint32_t fQh[8][4], fQl[8][4];
#pragma unroll
    for (int ks = 0; ks < 8; ++ks) {
        uint32_t aoff = (uint32_t)((wid * 16 + (q & 1) * 8 + rr) * (QSTR * 2)
                                   + (ks * 16 + (q >> 1) * 8) * 2);
        ldsm4(fQh[ks], aKh + aoff);
        ldsm4(fQl[ks], aKl + aoff);
    }
    __syncthreads();

    issueK(0); issueV(0, aV0); CP_COMMIT();

    float oacc[16][4];
#pragma unroll
    for (int nt = 0; nt < 16; nt++)
#pragma unroll
        for (int e = 0; e < 4; e++) oacc[nt][e] = 0.f;
    float m0 = -1e30f, m1 = -1e30f, l0 = 0.f, l1 = 0.f;

    const int NT = L_ / 64;
    for (int t = 0; t < NT; ++t) {
        const uint32_t vcur = (t & 1) ? aV1 : aV0;
        const uint32_t vnxt = (t & 1) ? aV0 : aV1;

        CP_WAIT0();
        __syncthreads();

        if (t + 1 < NT) { issueV(t + 1, vnxt); CP_COMMIT(); }

        float sacc[8][4];
#pragma unroll
        for (int nt = 0; nt < 8; nt++)
#pragma unroll
            for (int e = 0; e < 4; e++) sacc[nt][e] = 0.f;

#pragma unroll
        for (int ks = 0; ks < 8; ++ks) {
            uint32_t fKh[4][4], fKl[4][4];
#pragma unroll
            for (int np = 0; np < 4; ++np) {
                uint32_t boff = (uint32_t)((np * 16 + (q >> 1) * 8 + rr) * (QSTR * 2)
                                           + (ks * 16 + (q & 1) * 8) * 2);
                ldsm4(fKh[np], aKh + boff);
                ldsm4(fKl[np], aKl + boff);
            }
#pragma unroll
            for (int nt = 0; nt < 8; ++nt) {
                const uint32_t* bh = &fKh[nt >> 1][(nt & 1) * 2];
                const uint32_t* bl = &fKl[nt >> 1][(nt & 1) * 2];
                mma16816(sacc[nt], fQh[ks], bh);
                mma16816(sacc[nt], fQl[ks], bh);
                mma16816(sacc[nt], fQh[ks], bl);
            }
        }
        __syncthreads();
        if (t + 1 < NT) { issueK(t + 1); CP_COMMIT(); }

        float rmax0 = -1e30f, rmax1 = -1e30f;
#pragma unroll
        for (int nt = 0; nt < 8; ++nt) {
            rmax0 = fmaxf(rmax0, fmaxf(sacc[nt][0], sacc[nt][1]));
            rmax1 = fmaxf(rmax1, fmaxf(sacc[nt][2], sacc[nt][3]));
        }
        rmax0 = fmaxf(rmax0, __shfl_xor_sync(0xffffffffu, rmax0, 1));
        rmax0 = fmaxf(rmax0, __shfl_xor_sync(0xffffffffu, rmax0, 2));
        rmax1 = fmaxf(rmax1, __shfl_xor_sync(0xffffffffu, rmax1, 1));
        rmax1 = fmaxf(rmax1, __shfl_xor_sync(0xffffffffu, rmax1, 2));
        float mn0 = fmaxf(m0, rmax0), mn1 = fmaxf(m1, rmax1);
        float fact0 = __expf(m0 - mn0), fact1 = __expf(m1 - mn1);
        m0 = mn0; m1 = mn1;
        float sum0 = 0.f, sum1 = 0.f;
#pragma unroll
        for (int nt = 0; nt < 8; ++nt) {
            sacc[nt][0] = __expf(sacc[nt][0] - mn0); sum0 += sacc[nt][0];
            sacc[nt][1] = __expf(sacc[nt][1] - mn0); sum0 += sacc[nt][1];
            sacc[nt][2] = __expf(sacc[nt][2] - mn1); sum1 += sacc[nt][2];
            sacc[nt][3] = __expf(sacc[nt][3] - mn1); sum1 += sacc[nt][3];
        }
        sum0 += __shfl_xor_sync(0xffffffffu, sum0, 1);
        sum0 += __shfl_xor_sync(0xffffffffu, sum0, 2);
        sum1 += __shfl_xor_sync(0xffffffffu, sum1, 1);
        sum1 += __shfl_xor_sync(0xffffffffu, sum1, 2);
        l0 = l0 * fact0 + sum0;
        l1 = l1 * fact1 + sum1;
#pragma unroll
        for (int nt = 0; nt < 16; ++nt) {
            oacc[nt][0] *= fact0; oacc[nt][1] *= fact0;
            oacc[nt][2] *= fact1; oacc[nt][3] *= fact1;
        }

        const uint32_t aVhc = vcur, aVlc = vcur + 128 * VSTR * 2;
#pragma unroll
        for (int j = 0; j < 4; ++j) {
            uint32_t aPh[4], aPl[4];
#pragma unroll
            for (int hlf = 0; hlf < 2; ++hlf) {
                const float* p = sacc[2 * j + hlf];
                aPh[2 * hlf]     = pack_hi(p[0], p[1]);
                aPh[2 * hlf + 1] = pack_hi(p[2], p[3]);
                aPl[2 * hlf]     = pack_lo(p[0], p[1]);
                aPl[2 * hlf + 1] = pack_lo(p[2], p[3]);
            }
#pragma unroll
            for (int nn = 0; nn < 8; ++nn) {
                uint32_t fVh[4], fVl[4];
                uint32_t voff = (uint32_t)((nn * 16 + (q >> 1) * 8 + rr) * (VSTR * 2)
                                           + (j * 16 + (q & 1) * 8) * 2);
                ldsm4(fVh, aVhc + voff);
                ldsm4(fVl, aVlc + voff);
                mma16816(oacc[2 * nn], aPh, &fVh[0]);
                mma16816(oacc[2 * nn], aPl, &fVh[0]);
                mma16816(oacc[2 * nn], aPh, &fVl[0]);
                mma16816(oacc[2 * nn + 1], aPh, &fVh[2]);
                mma16816(oacc[2 * nn + 1], aPl, &fVh[2]);
                mma16816(oacc[2 * nn + 1], aPh, &fVl[2]);
            }
        }
    }

    float inv0 = 1.0f / l0, inv1 = 1.0f / l1;
    const int row0g = b * L_ + qt * 64 + wid * 16 + gr;
    __nv_bfloat16* oh0 = Oh + (size_t)row0g * HID_ + head * HDIM_;
    __nv_bfloat16* ol0 = Ol + (size_t)row0g * HID_ + head * HDIM_;
    __nv_bfloat16* oh1 = oh0 + (size_t)8 * HID_;
    __nv_bfloat16* ol1 = ol0 + (size_t)8 * HID_;
#pragma unroll
    for (int nt = 0; nt < 16; ++nt) {
        int col = nt * 8 + tg * 2;
        float v0 = oacc[nt][0] * inv0, v1 = oacc[nt][1] * inv0;
        float v2 = oacc[nt][2] * inv1, v3 = oacc[nt][3] * inv1;
        *(uint32_t*)(oh0 + col) = pack_hi(v0, v1);
        *(uint32_t*)(ol0 + col) = pack_lo(v0, v1);
        *(uint32_t*)(oh1 + col) = pack_hi(v2, v3);
        *(uint32_t*)(ol1 + col) = pack_lo(v2, v3);
    }
}

// ---------------------------------------------------------------------------
extern "C" void kernel_launch(void* const* d_in, const int* in_sizes, int n_in,
                              void* d_out, int out_size)
{
    const float* query = (const float*)d_in[0];
    const float* kv    = (const float*)d_in[1];
    const float* Wq    = (const float*)d_in[2];
    const float* bq    = (const float*)d_in[3];
    const float* Wkv   = (const float*)d_in[4];
    const float* bkv   = (const float*)d_in[5];
    const float* Wo    = (const float*)d_in[6];
    const float* bo    = (const float*)d_in[7];
    float* out = (float*)d_out;

    float* pv = nullptr;
    cudaGetSymbolAddress((void**)&pv, g_v);
    __nv_bfloat16 *qh, *ql, *kvh, *kvl, *ath, *atl;
    __nv_bfloat16 *wqh, *wql, *wkh, *wkl, *woh, *wol;
    __nv_bfloat16 *aqh, *aql, *akh, *akl, *avh, *avl;
    cudaGetSymbolAddress((void**)&qh,  g_qin_h);  cudaGetSymbolAddress((void**)&ql,  g_qin_l);
    cudaGetSymbolAddress((void**)&kvh, g_kvin_h); cudaGetSymbolAddress((void**)&kvl, g_kvin_l);
    cudaGetSymbolAddress((void**)&ath, g_att_h);  cudaGetSymbolAddress((void**)&atl, g_att_l);
    cudaGetSymbolAddress((void**)&wqh, g_wqt_h);  cudaGetSymbolAddress((void**)&wql, g_wqt_l);
    cudaGetSymbolAddress((void**)&wkh, g_wkvt_h); cudaGetSymbolAddress((void**)&wkl, g_wkvt_l);
    cudaGetSymbolAddress((void**)&woh, g_wot_h);  cudaGetSymbolAddress((void**)&wol, g_wot_l);
    cudaGetSymbolAddress((void**)&aqh, g_aqh);    cudaGetSymbolAddress((void**)&aql, g_aql);
    cudaGetSymbolAddress((void**)&akh, g_kh);     cudaGetSymbolAddress((void**)&akl, g_kl);
    cudaGetSymbolAddress((void**)&avh, g_vth);    cudaGetSymbolAddress((void**)&avl, g_vtl);

    cudaFuncSetAttribute(attn_tc_k, cudaFuncAttributeMaxDynamicSharedMemorySize,
                         ATT_SMEM);
    cudaFuncSetAttribute(hgemm_db_k, cudaFuncAttributeMaxDynamicSharedMemorySize,
                         GEMM_DSMEM);

    const int n_act4 = (MROWS * HID_) / 4;
    const int nb = (n_act4 + 255) / 256;
    const float qscale = 0.08838834764831845f;   // 1/sqrt(128)

    // 0: fused activation splits (query + kv)
    split2_k<<<2 * nb, 256>>>(query, qh, ql, kv, kvh, kvl, n_act4);
    // 1: fused weight transposes (Wq + Wkv + Wo)
    tsplit3_k<<<dim3(320, HID_ / 32), dim3(32, 8)>>>(Wq, wqh, wql,
                                                     Wkv, wkh, wkl,
                                                     Wo, woh, wol);
    // 2: Q projection -> scaled bf16 hi/lo
    hgemm_db_k<<<dim3(HID_ / 128, MROWS / 128), 256, GEMM_DSMEM>>>(
        qh, ql, wqh, wql, bq, nullptr, aqh, aql, qscale, MROWS, HID_, HID_, 1);
    // 3: KV projection -> K [b,kvh,l,d] bf16 hi/lo; V fp32  (ncu capture slot)
    hgemm_db_k<<<dim3(KVW / 128, MROWS / 128), 256, GEMM_DSMEM>>>(
        kvh, kvl, wkh, wkl, bkv, pv, akh, akl, 1.0f, MROWS, KVW, HID_, 2);
    // 4: V transpose prep
    vtprep_k<<<dim3(L_ / 32, HDIM_ / 32, B_ * NKV_), dim3(32, 8)>>>(pv, avh, avl);
    // 5: tensor-core attention
    attn_tc_k<<<dim3(L_ / 64, NHEAD_, B_), 128, ATT_SMEM>>>(
        aqh, aql, akh, akl, avh, avl, ath, atl);
    // 6: O projection -> fp32 out
    hgemm_db_k<<<dim3(HID_ / 128, MROWS / 128), 256, GEMM_DSMEM>>>(
        ath, atl, woh, wol, bo, out, nullptr, nullptr, 1.0f, MROWS, HID_, HID_, 0);
}

// round 16
// speedup vs baseline: 1.1317x; 1.0005x over previous
#include <cuda_runtime.h>
#include <cuda_bf16.h>
#include <cstdint>
#include <math.h>

#define B_     2
#define L_     2048
#define HID_   4096
#define NHEAD_ 32
#define NKV_   8
#define HDIM_  128
#define MROWS  (B_*L_)          // 4096
#define KVW    (2*NKV_*HDIM_)   // 2048
#define VW     (NKV_*HDIM_)     // 1024

// ------------------------- device scratch (no allocs) -----------------------
__device__ __align__(256) float g_v  [(size_t)MROWS * VW];   // V fp32 (16 MB)

__device__ __align__(256) __nv_bfloat16 g_qin_h [(size_t)MROWS * HID_];
__device__ __align__(256) __nv_bfloat16 g_qin_l [(size_t)MROWS * HID_];
__device__ __align__(256) __nv_bfloat16 g_kvin_h[(size_t)MROWS * HID_];
__device__ __align__(256) __nv_bfloat16 g_kvin_l[(size_t)MROWS * HID_];
__device__ __align__(256) __nv_bfloat16 g_att_h [(size_t)MROWS * HID_];
__device__ __align__(256) __nv_bfloat16 g_att_l [(size_t)MROWS * HID_];
__device__ __align__(256) __nv_bfloat16 g_wqt_h [(size_t)HID_ * HID_];
__device__ __align__(256) __nv_bfloat16 g_wqt_l [(size_t)HID_ * HID_];
__device__ __align__(256) __nv_bfloat16 g_wkvt_h[(size_t)KVW  * HID_];
__device__ __align__(256) __nv_bfloat16 g_wkvt_l[(size_t)KVW  * HID_];
__device__ __align__(256) __nv_bfloat16 g_wot_h [(size_t)HID_ * HID_];
__device__ __align__(256) __nv_bfloat16 g_wot_l [(size_t)HID_ * HID_];
// attention operands (bf16 hi/lo)
__device__ __align__(256) __nv_bfloat16 g_aqh[(size_t)MROWS * HID_];  // scaled Q
__device__ __align__(256) __nv_bfloat16 g_aql[(size_t)MROWS * HID_];
__device__ __align__(256) __nv_bfloat16 g_kh [(size_t)B_*NKV_*L_*HDIM_]; // [b,kvh,l,d]
__device__ __align__(256) __nv_bfloat16 g_kl [(size_t)B_*NKV_*L_*HDIM_];
__device__ __align__(256) __nv_bfloat16 g_vth[(size_t)B_*NKV_*HDIM_*L_]; // [b,kvh,d,l]
__device__ __align__(256) __nv_bfloat16 g_vtl[(size_t)B_*NKV_*HDIM_*L_];

// ------------------------------ PTX helpers ---------------------------------
__device__ __forceinline__ uint32_t smem_u32(const void* p) {
    uint32_t a;
    asm("{ .reg .u64 t; cvta.to.shared.u64 t, %1; cvt.u32.u64 %0, t; }"
        : "=r"(a) : "l"(p));
    return a;
}

__device__ __forceinline__ void ldsm4(uint32_t* r, uint32_t addr) {
    asm volatile("ldmatrix.sync.aligned.m8n8.x4.shared.b16 {%0,%1,%2,%3}, [%4];"
                 : "=r"(r[0]), "=r"(r[1]), "=r"(r[2]), "=r"(r[3]) : "r"(addr));
}

__device__ __forceinline__ void mma16816(float* d, const uint32_t* a,
                                         const uint32_t* b) {
    asm volatile(
        "mma.sync.aligned.m16n8k16.row.col.f32.bf16.bf16.f32 "
        "{%0,%1,%2,%3}, {%4,%5,%6,%7}, {%8,%9}, {%0,%1,%2,%3};"
        : "+f"(d[0]), "+f"(d[1]), "+f"(d[2]), "+f"(d[3])
        : "r"(a[0]), "r"(a[1]), "r"(a[2]), "r"(a[3]), "r"(b[0]), "r"(b[1]));
}

#define CP16(saddr, gaddr) \
    asm volatile("cp.async.cg.shared.global [%0], [%1], 16;" \
                 :: "r"(saddr), "l"(gaddr) : "memory")
#define CP_COMMIT()  asm volatile("cp.async.commit_group;" ::: "memory")
#define CP_WAIT0()   asm volatile("cp.async.wait_group 0;" ::: "memory")

__device__ __forceinline__ unsigned short f2bf_bits(float x) {
    __nv_bfloat16 h = __float2bfloat16(x);
    return *(unsigned short*)&h;
}
__device__ __forceinline__ float bf_bits2f(unsigned short b) {
    __nv_bfloat16 h = *(__nv_bfloat16*)&b;
    return __bfloat162float(h);
}
__device__ __forceinline__ uint32_t pack_hi(float a, float b) {
    return (uint32_t)f2bf_bits(a) | ((uint32_t)f2bf_bits(b) << 16);
}
__device__ __forceinline__ uint32_t pack_lo(float a, float b) {
    unsigned short ha = f2bf_bits(a), hb = f2bf_bits(b);
    return (uint32_t)f2bf_bits(a - bf_bits2f(ha))
         | ((uint32_t)f2bf_bits(b - bf_bits2f(hb)) << 16);
}

// ---------------------------- fused prep kernels ----------------------------
__global__ __launch_bounds__(256) void split2_k(
    const float* __restrict__ inA, __nv_bfloat16* __restrict__ hiA,
    __nv_bfloat16* __restrict__ loA,
    const float* __restrict__ inB, __nv_bfloat16* __restrict__ hiB,
    __nv_bfloat16* __restrict__ loB, int n4)
{
    int nb = (n4 + 255) >> 8;
    const float* in; __nv_bfloat16 *hi, *lo;
    int i;
    if (blockIdx.x < nb) {
        in = inA; hi = hiA; lo = loA;
        i = blockIdx.x * 256 + threadIdx.x;
    } else {
        in = inB; hi = hiB; lo = loB;
        i = (blockIdx.x - nb) * 256 + threadIdx.x;
    }
    if (i >= n4) return;
    float4 v = ((const float4*)in)[i];
    ((uint2*)hi)[i] = make_uint2(pack_hi(v.x, v.y), pack_hi(v.z, v.w));
    ((uint2*)lo)[i] = make_uint2(pack_lo(v.x, v.y), pack_lo(v.z, v.w));
}

__global__ __launch_bounds__(256) void tsplit3_k(
    const float* __restrict__ Wq_, __nv_bfloat16* __restrict__ TqH,
    __nv_bfloat16* __restrict__ TqL,
    const float* __restrict__ Wk_, __nv_bfloat16* __restrict__ TkH,
    __nv_bfloat16* __restrict__ TkL,
    const float* __restrict__ Wo_, __nv_bfloat16* __restrict__ ToH,
    __nv_bfloat16* __restrict__ ToL)
{
    __shared__ float t[32][33];
    const int K = HID_;
    const float* W; __nv_bfloat16 *Th, *Tl;
    int N, bxl;
    int bx = blockIdx.x;
    if (bx < 128)      { W = Wq_; Th = TqH; Tl = TqL; N = HID_; bxl = bx; }
    else if (bx < 192) { W = Wk_; Th = TkH; Tl = TkL; N = KVW;  bxl = bx - 128; }
    else               { W = Wo_; Th = ToH; Tl = ToL; N = HID_; bxl = bx - 192; }

    int tx = threadIdx.x, ty = threadIdx.y;   // 32 x 8
    int n0 = bxl * 32, k0 = blockIdx.y * 32;
#pragma unroll
    for (int i = 0; i < 4; i++)
        t[ty + 8 * i][tx] = W[(size_t)(k0 + ty + 8 * i) * N + n0 + tx];
    __syncthreads();
#pragma unroll
    for (int i = 0; i < 4; i++) {
        float v = t[tx][ty + 8 * i];
        unsigned short h = f2bf_bits(v);
        unsigned short l = f2bf_bits(v - bf_bits2f(h));
        size_t o = (size_t)(n0 + ty + 8 * i) * K + k0 + tx;
        Th[o] = *(__nv_bfloat16*)&h; Tl[o] = *(__nv_bfloat16*)&l;
    }
}

// V prep: g_v fp32 [b*L+l][kvh*128+d] -> vth/vtl [b,kvh,d,l] bf16 (transpose)
__global__ __launch_bounds__(256) void vtprep_k(const float* __restrict__ V,
                                                __nv_bfloat16* __restrict__ Vh,
                                                __nv_bfloat16* __restrict__ Vl)
{
    __shared__ float t[32][33];
    int tx = threadIdx.x, ty = threadIdx.y;
    int l0 = blockIdx.x * 32, d0 = blockIdx.y * 32;
    int bk = blockIdx.z;
    int b = bk >> 3, kvh = bk & 7;
#pragma unroll
    for (int i = 0; i < 4; i++)
        t[ty + 8 * i][tx] = V[(size_t)(b * L_ + l0 + ty + 8 * i) * VW
                              + kvh * HDIM_ + d0 + tx];
    __syncthreads();
#pragma unroll
    for (int i = 0; i < 4; i++) {
        float v = t[tx][ty + 8 * i];
        unsigned short h = f2bf_bits(v);
        unsigned short l = f2bf_bits(v - bf_bits2f(h));
        size_t o = ((size_t)bk * HDIM_ + d0 + ty + 8 * i) * L_ + l0 + tx;
        Vh[o] = *(__nv_bfloat16*)&h; Vl[o] = *(__nv_bfloat16*)&l;
    }
}

// ---------------- HMMA GEMM, 2-stage cp.async, single-sync, 2 CTAs/SM -------
// (byte-identical to the validated Round-12 kernel)
#define SSTRIDE 40
#define TILEB   10240u
#define STAGEB  (4u * TILEB)           // 40960 B per stage
#define GEMM_DSMEM (2 * (int)STAGEB)   // 81920 B

__global__ __launch_bounds__(256, 2) void hgemm_db_k(
    const __nv_bfloat16* __restrict__ Ah, const __nv_bfloat16* __restrict__ Al,
    const __nv_bfloat16* __restrict__ Bh, const __nv_bfloat16* __restrict__ Bl,
    const float* __restrict__ bias,
    float* __restrict__ C,
    __nv_bfloat16* __restrict__ Ch, __nv_bfloat16* __restrict__ Cl,
    float oscale, int M, int N, int K, int mode)
{
    extern __shared__ __nv_bfloat16 dynsm[];
    const uint32_t sbase = smem_u32(dynsm);

    const int tid  = threadIdx.x;
    const int wid  = tid >> 5, lane = tid & 31;
    const int gr   = lane >> 2, tg = lane & 3;
    const int wm   = (wid & 1) * 64;
    const int wn   = (wid >> 1) * 32;
    const int row0 = blockIdx.y * 128, col0 = blockIdx.x * 128;
    const int q    = lane >> 3, rr = lane & 7;

    float acc[4][4][4];
#pragma unroll
    for (int mt = 0; mt < 4; mt++)
#pragma unroll
        for (int nt = 0; nt < 4; nt++)
#pragma unroll
            for (int e = 0; e < 4; e++) acc[mt][nt][e] = 0.f;

    const int lr0 = tid >> 2, lc0 = (tid & 3) * 8;
    const int lr1 = lr0 + 64;
    const uint32_t so0 = (uint32_t)(lr0 * SSTRIDE + lc0) * 2;
    const uint32_t so1 = (uint32_t)(lr1 * SSTRIDE + lc0) * 2;
    const __nv_bfloat16* pAh = Ah + (size_t)row0 * K;
    const __nv_bfloat16* pAl = Al + (size_t)row0 * K;
    const __nv_bfloat16* pBh = Bh + (size_t)col0 * K;
    const __nv_bfloat16* pBl = Bl + (size_t)col0 * K;

    const int niter = K >> 5;

    auto issue = [&](uint32_t bb, int it) {
        const int kt = it << 5;
        CP16(bb + so0,              pAh + (size_t)lr0 * K + kt + lc0);
        CP16(bb + so1,              pAh + (size_t)lr1 * K + kt + lc0);
        CP16(bb + TILEB + so0,      pAl + (size_t)lr0 * K + kt + lc0);
        CP16(bb + TILEB + so1,      pAl + (size_t)lr1 * K + kt + lc0);
        CP16(bb + 2 * TILEB + so0,  pBh + (size_t)lr0 * K + kt + lc0);
        CP16(bb + 2 * TILEB + so1,  pBh + (size_t)lr1 * K + kt + lc0);
        CP16(bb + 3 * TILEB + so0,  pBl + (size_t)lr0 * K + kt + lc0);
        CP16(bb + 3 * TILEB + so1,  pBl + (size_t)lr1 * K + kt + lc0);
    };

    issue(sbase, 0); CP_COMMIT();

    uint32_t s = 0;
    for (int it = 0; it < niter; ++it) {
        CP_WAIT0();
        __syncthreads();
        if (it + 1 < niter) { issue(sbase + (s ^ STAGEB), it + 1); CP_COMMIT(); }

        const uint32_t aAh = sbase + s;
        const uint32_t aAl = aAh + TILEB;
        const uint32_t aBh = aAh + 2 * TILEB;
        const uint32_t aBl = aAh + 3 * TILEB;

#pragma unroll
        for (int ks = 0; ks < 2; ++ks) {
            uint32_t fBh0[4], fBh1[4], fBl0[4], fBl1[4];
            {
                uint32_t offb0 = (uint32_t)((wn + (q >> 1) * 8 + rr) * (SSTRIDE * 2)
                                            + (ks * 16 + (q & 1) * 8) * 2);
                uint32_t offb1 = offb0 + 16u * (SSTRIDE * 2);
                ldsm4(fBh0, aBh + offb0);
                ldsm4(fBh1, aBh + offb1);
                ldsm4(fBl0, aBl + offb0);
                ldsm4(fBl1, aBl + offb1);
            }
#pragma unroll
            for (int mt = 0; mt < 4; ++mt) {
                uint32_t offa = (uint32_t)((wm + mt * 16 + (q & 1) * 8 + rr) * (SSTRIDE * 2)
                                           + (ks * 16 + (q >> 1) * 8) * 2);
                uint32_t fA[4];
                ldsm4(fA, aAh + offa);
                mma16816(acc[mt][0], fA, &fBh0[0]);
                mma16816(acc[mt][1], fA, &fBh0[2]);
                mma16816(acc[mt][2], fA, &fBh1[0]);
                mma16816(acc[mt][3], fA, &fBh1[2]);
                mma16816(acc[mt][0], fA, &fBl0[0]);
                mma16816(acc[mt][1], fA, &fBl0[2]);
                mma16816(acc[mt][2], fA, &fBl1[0]);
                mma16816(acc[mt][3], fA, &fBl1[2]);
                uint32_t fA2[4];
                ldsm4(fA2, aAl + offa);
                mma16816(acc[mt][0], fA2, &fBh0[0]);
                mma16816(acc[mt][1], fA2, &fBh0[2]);
                mma16816(acc[mt][2], fA2, &fBh1[0]);
                mma16816(acc[mt][3], fA2, &fBh1[2]);
            }
        }
        s ^= STAGEB;
    }

    // ---- epilogue ----
    const bool kv_kpart = (mode == 2) && (col0 < VW);
    if (mode == 1 || kv_kpart) {
#pragma unroll
        for (int mt = 0; mt < 4; ++mt) {
#pragma unroll
            for (int nt = 0; nt < 4; ++nt) {
                int r = row0 + wm + mt * 16 + gr;
                int c = col0 + wn + nt * 8 + tg * 2;
                float b0 = bias[c], b1 = bias[c + 1];
                float v0 = (acc[mt][nt][0] + b0) * oscale;
                float v1 = (acc[mt][nt][1] + b1) * oscale;
                float v2 = (acc[mt][nt][2] + b0) * oscale;
                float v3 = (acc[mt][nt][3] + b1) * oscale;
                size_t o0, o1;
                if (kv_kpart) {
                    int bb = r >> 11, ll = r & (L_ - 1);
                    int kvhh = c >> 7, d = c & (HDIM_ - 1);
                    o0 = ((size_t)(bb * NKV_ + kvhh) * L_ + ll) * HDIM_ + d;
                    o1 = o0 + (size_t)8 * HDIM_;
                } else {
                    o0 = (size_t)r * N + c;
                    o1 = (size_t)(r + 8) * N + c;
                }
                *(uint32_t*)(Ch + o0) = pack_hi(v0, v1);
                *(uint32_t*)(Cl + o0) = pack_lo(v0, v1);
                *(uint32_t*)(Ch + o1) = pack_hi(v2, v3);
                *(uint32_t*)(Cl + o1) = pack_lo(v2, v3);
            }
        }
    } else {
        const int cw    = (mode == 2) ? VW : N;
        const int cbase = (mode == 2) ? (col0 - VW) : col0;
#pragma unroll
        for (int mt = 0; mt < 4; ++mt) {
#pragma unroll
            for (int nt = 0; nt < 4; ++nt) {
                int r = row0 + wm + mt * 16 + gr;
                int c = col0 + wn + nt * 8 + tg * 2;
                float b0 = bias[c], b1 = bias[c + 1];
                int cc = cbase + wn + nt * 8 + tg * 2;
                float2 v0 = make_float2(acc[mt][nt][0] + b0, acc[mt][nt][1] + b1);
                float2 v1 = make_float2(acc[mt][nt][2] + b0, acc[mt][nt][3] + b1);
                *(float2*)(C + (size_t)r * cw + cc) = v0;
                *(float2*)(C + (size_t)(r + 8) * cw + cc) = v1;
            }
        }
    }
}

// ---------------------------------------------------------------------------
// Tensor-core flash attention — R12/R15 structure; softmax in base-2 domain
// (log2e folded into Q scale) so every exp is a bare MUFU.EX2.
// ---------------------------------------------------------------------------
#define QSTR 136
#define VSTR 72
#define KPAIR_B  (2u * 64 * QSTR * 2)
#define VPAIR_B  (2u * 128 * VSTR * 2)
#define ATT_SMEM ((int)(KPAIR_B + 2 * VPAIR_B))   // 108544 B

__global__ __launch_bounds__(128) void attn_tc_k(
    const __nv_bfloat16* __restrict__ Qh, const __nv_bfloat16* __restrict__ Ql,
    const __nv_bfloat16* __restrict__ Kh, const __nv_bfloat16* __restrict__ Kl,
    const __nv_bfloat16* __restrict__ Vh, const __nv_bfloat16* __restrict__ Vl,
    __nv_bfloat16* __restrict__ Oh, __nv_bfloat16* __restrict__ Ol)
{
    extern __shared__ __nv_bfloat16 smem_bf[];
    const uint32_t sb  = smem_u32(smem_bf);
    const uint32_t aKh = sb;
    const uint32_t aKl = aKh + 64 * QSTR * 2;
    const uint32_t aV0 = aKl + 64 * QSTR * 2;
    const uint32_t aV1 = aV0 + VPAIR_B;

    const int b = blockIdx.z, head = blockIdx.y, qt = blockIdx.x;
    const int kvh = head >> 2;
    const int tid = threadIdx.x;
    const int wid = tid >> 5, lane = tid & 31;
    const int q = lane >> 3, rr = lane & 7;
    const int gr = lane >> 2, tg = lane & 3;

    const __nv_bfloat16* kbh = Kh + (size_t)(b * NKV_ + kvh) * L_ * HDIM_;
    const __nv_bfloat16* kbl = Kl + (size_t)(b * NKV_ + kvh) * L_ * HDIM_;
    const __nv_bfloat16* vbh = Vh + (size_t)(b * NKV_ + kvh) * HDIM_ * L_;
    const __nv_bfloat16* vbl = Vl + (size_t)(b * NKV_ + kvh) * HDIM_ * L_;

    auto issueK = [&](int t) {
#pragma unroll
        for (int i = 0; i < 8; i++) {
            int idx = tid + i * 128;
            int row = idx >> 4, ch = idx & 15;
            uint32_t so = (uint32_t)(row * QSTR + ch * 8) * 2;
            CP16(aKh + so, kbh + (size_t)(t * 64 + row) * HDIM_ + ch * 8);
            CP16(aKl + so, kbl + (size_t)(t * 64 + row) * HDIM_ + ch * 8);
        }
    };
    auto issueV = [&](int t, uint32_t vb) {
#pragma unroll
        for (int i = 0; i < 8; i++) {
            int idx = tid + i * 128;
            int vrow = idx >> 3, vch = idx & 7;
            uint32_t so = (uint32_t)(vrow * VSTR + vch * 8) * 2;
            CP16(vb + so,                   vbh + (size_t)vrow * L_ + t * 64 + vch * 8);
            CP16(vb + 128 * VSTR * 2 + so,  vbl + (size_t)vrow * L_ + t * 64 + vch * 8);
        }
    };

    {
        const __nv_bfloat16* qbh = Qh + (size_t)(b * L_ + qt * 64) * HID_ + head * HDIM_;
        const __nv_bfloat16* qbl = Ql + (size_t)(b * L_ + qt * 64) * HID_ + head * HDIM_;
#pragma unroll
        for (int i = 0; i < 8; i++) {
            int idx = tid + i * 128;
            int row = idx >> 4, ch = idx & 15;
            uint32_t so = (uint32_t)(row * QSTR + ch * 8) * 2;
            CP16(aKh + so, qbh + (size_t)row * HID_ + ch * 8);
            CP16(aKl + so, qbl + (size_t)row * HID_ + ch * 8);
        }
        CP_COMMIT(); CP_WAIT0();
    }
    __syncthreads();
    uint32_t fQh[8][4], fQl[8][4];
#pragma unroll
    for (int ks = 0; ks < 8; ++ks) {
        uint32_t aoff = (uint32_t)((wid * 16 + (q & 1) * 8 + rr) * (QSTR * 2)
                                   + (ks * 16 + (q >> 1) * 8) * 2);
        ldsm4(fQh[ks], aKh + aoff);
        ldsm4(fQl[ks], aKl + aoff);
    }
    __syncthreads();

    issueK(0); issueV(0, aV0); CP_COMMIT();

    float oacc[16][4];
#pragma unroll
    for (int nt = 0; nt < 16; nt++)
#pragma unroll
        for (int e = 0; e < 4; e++) oacc[nt][e] = 0.f;
    float m0 = -1e30f, m1 = -1e30f, l0 = 0.f, l1 = 0.f;

    const int NT = L_ / 64;
    for (int t = 0; t < NT; ++t) {
        const uint32_t vcur = (t & 1) ? aV1 : aV0;
        const uint32_t vnxt = (t & 1) ? aV0 : aV1;

        CP_WAIT0();
        __syncthreads();

        if (t + 1 < NT) { issueV(t + 1, vnxt); CP_COMMIT(); }

        float sacc[8][4];
#pragma unroll
        for (int nt = 0; nt < 8; nt++)
#pragma unroll
            for (int e = 0; e < 4; e++) sacc[nt][e] = 0.f;

#pragma unroll
        for (int ks = 0; ks < 8; ++ks) {
            uint32_t fKh[4][4], fKl[4][4];
#pragma unroll
            for (int np = 0; np < 4; ++np) {
                uint32_t boff = (uint32_t)((np * 16 + (q >> 1) * 8 + rr) * (QSTR * 2)
                                           + (ks * 16 + (q & 1) * 8) * 2);
                ldsm4(fKh[np], aKh + boff);
                ldsm4(fKl[np], aKl + boff);
            }
#pragma unroll
            for (int nt = 0; nt < 8; ++nt) {
                const uint32_t* bh = &fKh[nt >> 1][(nt & 1) * 2];
                const uint32_t* bl = &fKl[nt >> 1][(nt & 1) * 2];
                mma16816(sacc[nt], fQh[ks], bh);
                mma16816(sacc[nt], fQl[ks], bh);
                mma16816(sacc[nt], fQh[ks], bl);
            }
        }
        __syncthreads();
        if (t + 1 < NT) { issueK(t + 1); CP_COMMIT(); }

        // ---- online softmax in base-2 logit domain (exp2f = bare MUFU) ----
        float rmax0 = -1e30f, rmax1 = -1e30f;
#pragma unroll
        for (int nt = 0; nt < 8; ++nt) {
            rmax0 = fmaxf(rmax0, fmaxf(sacc[nt][0], sacc[nt][1]));
            rmax1 = fmaxf(rmax1, fmaxf(sacc[nt][2], sacc[nt][3]));
        }
        rmax0 = fmaxf(rmax0, __shfl_xor_sync(0xffffffffu, rmax0, 1));
        rmax0 = fmaxf(rmax0, __shfl_xor_sync(0xffffffffu, rmax0, 2));
        rmax1 = fmaxf(rmax1, __shfl_xor_sync(0xffffffffu, rmax1, 1));
        rmax1 = fmaxf(rmax1, __shfl_xor_sync(0xffffffffu, rmax1, 2));
        float mn0 = fmaxf(m0, rmax0), mn1 = fmaxf(m1, rmax1);
        float fact0 = exp2f(m0 - mn0), fact1 = exp2f(m1 - mn1);
        m0 = mn0; m1 = mn1;
        float sum0 = 0.f, sum1 = 0.f;
#pragma unroll
        for (int nt = 0; nt < 8; ++nt) {
            sacc[nt][0] = exp2f(sacc[nt][0] - mn0); sum0 += sacc[nt][0];
            sacc[nt][1] = exp2f(sacc[nt][1] - mn0); sum0 += sacc[nt][1];
            sacc[nt][2] = exp2f(sacc[nt][2] - mn1); sum1 += sacc[nt][2];
            sacc[nt][3] = exp2f(sacc[nt][3] - mn1); sum1 += sacc[nt][3];
        }
        sum0 += __shfl_xor_sync(0xffffffffu, sum0, 1);
        sum0 += __shfl_xor_sync(0xffffffffu, sum0, 2);
        sum1 += __shfl_xor_sync(0xffffffffu, sum1, 1);
        sum1 += __shfl_xor_sync(0xffffffffu, sum1, 2);
        l0 = l0 * fact0 + sum0;
        l1 = l1 * fact1 + sum1;
#pragma unroll
        for (int nt = 0; nt < 16; ++nt) {
            oacc[nt][0] *= fact0; oacc[nt][1] *= fact0;
            oacc[nt][2] *= fact1; oacc[nt][3] *= fact1;
        }

        const uint32_t aVhc = vcur, aVlc = vcur + 128 * VSTR * 2;
#pragma unroll
        for (int j = 0; j < 4; ++j) {
            uint32_t aPh[4], aPl[4];
#pragma unroll
            for (int hlf = 0; hlf < 2; ++hlf) {
                const float* p = sacc[2 * j + hlf];
                aPh[2 * hlf]     = pack_hi(p[0], p[1]);
                aPh[2 * hlf + 1] = pack_hi(p[2], p[3]);
                aPl[2 * hlf]     = pack_lo(p[0], p[1]);
                aPl[2 * hlf + 1] = pack_lo(p[2], p[3]);
            }
#pragma unroll
            for (int nn = 0; nn < 8; ++nn) {
                uint32_t fVh[4], fVl[4];
                uint32_t voff = (uint32_t)((nn * 16 + (q >> 1) * 8 + rr) * (VSTR * 2)
                                           + (j * 16 + (q & 1) * 8) * 2);
                ldsm4(fVh, aVhc + voff);
                ldsm4(fVl, aVlc + voff);
                mma16816(oacc[2 * nn], aPh, &fVh[0]);
                mma16816(oacc[2 * nn], aPl, &fVh[0]);
                mma16816(oacc[2 * nn], aPh, &fVl[0]);
                mma16816(oacc[2 * nn + 1], aPh, &fVh[2]);
                mma16816(oacc[2 * nn + 1], aPl, &fVh[2]);
                mma16816(oacc[2 * nn + 1], aPh, &fVl[2]);
            }
        }
    }

    float inv0 = 1.0f / l0, inv1 = 1.0f / l1;
    const int row0g = b * L_ + qt * 64 + wid * 16 + gr;
    __nv_bfloat16* oh0 = Oh + (size_t)row0g * HID_ + head * HDIM_;
    __nv_bfloat16* ol0 = Ol + (size_t)row0g * HID_ + head * HDIM_;
    __nv_bfloat16* oh1 = oh0 + (size_t)8 * HID_;
    __nv_bfloat16* ol1 = ol0 + (size_t)8 * HID_;
#pragma unroll
    for (int nt = 0; nt < 16; ++nt) {
        int col = nt * 8 + tg * 2;
        float v0 = oacc[nt][0] * inv0, v1 = oacc[nt][1] * inv0;
        float v2 = oacc[nt][2] * inv1, v3 = oacc[nt][3] * inv1;
        *(uint32_t*)(oh0 + col) = pack_hi(v0, v1);
        *(uint32_t*)(ol0 + col) = pack_lo(v0, v1);
        *(uint32_t*)(oh1 + col) = pack_hi(v2, v3);
        *(uint32_t*)(ol1 + col) = pack_lo(v2, v3);
    }
}

// ---------------------------------------------------------------------------
extern "C" void kernel_launch(void* const* d_in, const int* in_sizes, int n_in,
                              void* d_out, int out_size)
{
    const float* query = (const float*)d_in[0];
    const float* kv    = (const float*)d_in[1];
    const float* Wq    = (const float*)d_in[2];
    const float* bq    = (const float*)d_in[3];
    const float* Wkv   = (const float*)d_in[4];
    const float* bkv   = (const float*)d_in[5];
    const float* Wo    = (const float*)d_in[6];
    const float* bo    = (const float*)d_in[7];
    float* out = (float*)d_out;

    float* pv = nullptr;
    cudaGetSymbolAddress((void**)&pv, g_v);
    __nv_bfloat16 *qh, *ql, *kvh, *kvl, *ath, *atl;
    __nv_bfloat16 *wqh, *wql, *wkh, *wkl, *woh, *wol;
    __nv_bfloat16 *aqh, *aql, *akh, *akl, *avh, *avl;
    cudaGetSymbolAddress((void**)&qh,  g_qin_h);  cudaGetSymbolAddress((void**)&ql,  g_qin_l);
    cudaGetSymbolAddress((void**)&kvh, g_kvin_h); cudaGetSymbolAddress((void**)&kvl, g_kvin_l);
    cudaGetSymbolAddress((void**)&ath, g_att_h);  cudaGetSymbolAddress((void**)&atl, g_att_l);
    cudaGetSymbolAddress((void**)&wqh, g_wqt_h);  cudaGetSymbolAddress((void**)&wql, g_wqt_l);
    cudaGetSymbolAddress((void**)&wkh, g_wkvt_h); cudaGetSymbolAddress((void**)&wkl, g_wkvt_l);
    cudaGetSymbolAddress((void**)&woh, g_wot_h);  cudaGetSymbolAddress((void**)&wol, g_wot_l);
    cudaGetSymbolAddress((void**)&aqh, g_aqh);    cudaGetSymbolAddress((void**)&aql, g_aql);
    cudaGetSymbolAddress((void**)&akh, g_kh);     cudaGetSymbolAddress((void**)&akl, g_kl);
    cudaGetSymbolAddress((void**)&avh, g_vth);    cudaGetSymbolAddress((void**)&avl, g_vtl);

    cudaFuncSetAttribute(attn_tc_k, cudaFuncAttributeMaxDynamicSharedMemorySize,
                         ATT_SMEM);
    cudaFuncSetAttribute(hgemm_db_k, cudaFuncAttributeMaxDynamicSharedMemorySize,
                         GEMM_DSMEM);

    const int n_act4 = (MROWS * HID_) / 4;
    const int nb = (n_act4 + 255) / 256;
    // 1/sqrt(128) * log2(e): softmax computed in base-2 logit domain
    const float qscale = 0.08838834764831845f * 1.4426950408889634f;

    // 0: fused activation splits (query + kv)
    split2_k<<<2 * nb, 256>>>(query, qh, ql, kv, kvh, kvl, n_act4);
    // 1: fused weight transposes (Wq + Wkv + Wo)
    tsplit3_k<<<dim3(320, HID_ / 32), dim3(32, 8)>>>(Wq, wqh, wql,
                                                     Wkv, wkh, wkl,
                                                     Wo, woh, wol);
    // 2: Q projection -> (log2e/sqrt(d))-scaled bf16 hi/lo
    hgemm_db_k<<<dim3(HID_ / 128, MROWS / 128), 256, GEMM_DSMEM>>>(
        qh, ql, wqh, wql, bq, nullptr, aqh, aql, qscale, MROWS, HID_, HID_, 1);
    // 3: KV projection -> K [b,kvh,l,d] bf16 hi/lo; V fp32
    hgemm_db_k<<<dim3(KVW / 128, MROWS / 128), 256, GEMM_DSMEM>>>(
        kvh, kvl, wkh, wkl, bkv, pv, akh, akl, 1.0f, MROWS, KVW, HID_, 2);
    // 4: V transpose prep
    vtprep_k<<<dim3(L_ / 32, HDIM_ / 32, B_ * NKV_), dim3(32, 8)>>>(pv, avh, avl);
    // 5: tensor-core attention (base-2 softmax)
    attn_tc_k<<<dim3(L_ / 64, NHEAD_, B_), 128, ATT_SMEM>>>(
        aqh, aql, akh, akl, avh, avl, ath, atl);
    // 6: O projection -> fp32 out
    hgemm_db_k<<<dim3(HID_ / 128, MROWS / 128), 256, GEMM_DSMEM>>>(
        ath, atl, woh, wol, bo, out, nullptr, nullptr, 1.0f, MROWS, HID_, HID_, 0);
}